// round 14
// baseline (speedup 1.0000x reference)
#include <cuda_runtime.h>
#include <cuda_fp16.h>

#define Bsz  64
#define Tt   128
#define Cc   384
#define Hh   6
#define DHh  64
#define Ll   6
#define FFf  1536
#define Vv   25000
#define NTOK (Bsz * Tt)
#define LN_EPS 1e-5f
#define NBLK_LM 196              // ceil(25000/128)

typedef __half fh;
typedef __half2 fh2;

// ---------------- scratch (device globals: allocation-free) ----------------
__device__ float g_x[NTOK * Cc];
__device__ float g_q[NTOK * Cc];
__device__ float g_k[NTOK * Cc];
__device__ float g_v[NTOK * Cc];
__device__ float g_nll[NTOK];
__device__ float2 g_lsep[(size_t)NTOK * NBLK_LM];

// fp16 activations
__device__ fh g_ha[NTOK * Cc];       // LN outputs
__device__ fh g_at[NTOK * Cc];       // attention outputs
__device__ fh g_ff[NTOK * FFf];      // FFN1 outputs

// transposed fp16 weights [N][K] (hi used by GEMMs; lo kept by wsplit)
__device__ fh g_wqh[Ll * Cc * Cc],  g_wql[Ll * Cc * Cc];
__device__ fh g_wkh[Ll * Cc * Cc],  g_wkl[Ll * Cc * Cc];
__device__ fh g_wvh[Ll * Cc * Cc],  g_wvl[Ll * Cc * Cc];
__device__ fh g_woh[Ll * Cc * Cc],  g_wol[Ll * Cc * Cc];
__device__ fh g_w1h[Ll * Cc * FFf], g_w1l[Ll * Cc * FFf];
__device__ fh g_w2h[Ll * FFf * Cc], g_w2l[Ll * FFf * Cc];
__device__ fh g_lmh[(size_t)Vv * Cc], g_lml[(size_t)Vv * Cc];

__device__ __forceinline__ void cvt_hl(float x, fh& h, fh& l) {
    h = __float2half_rn(x);
    l = __float2half_rn(x - __half2float(h));
}

__device__ __forceinline__ void lse_up(float& m, float& s, float v) {
    if (v > m) { s = s * __expf(m - v) + 1.f; m = v; }
    else       { s += __expf(v - m); }
}
__device__ __forceinline__ void lse_merge(float& m, float& s, float m2, float s2) {
    float nm = fmaxf(m, m2);
    s = s * __expf(m - nm) + s2 * __expf(m2 - nm);
    m = nm;
}

// ---------------- weight transpose + split: w[K][N] -> th/tl[N][K] ---------
__global__ void wsplit_t(const float* __restrict__ w, fh* __restrict__ th,
                         fh* __restrict__ tl, int K, int N) {
    __shared__ float tile[32][33];
    int l = blockIdx.z;
    const float* wp = w + (size_t)l * K * N;
    fh* thp = th + (size_t)l * K * N;
    fh* tlp = tl + (size_t)l * K * N;
    int n0 = blockIdx.x * 32, k0 = blockIdx.y * 32;
    int tx = threadIdx.x, ty = threadIdx.y;  // 32 x 8
#pragma unroll
    for (int i = 0; i < 4; i++) {
        int k = k0 + ty + 8 * i, n = n0 + tx;
        tile[ty + 8 * i][tx] = (k < K && n < N) ? wp[(size_t)k * N + n] : 0.f;
    }
    __syncthreads();
#pragma unroll
    for (int i = 0; i < 4; i++) {
        int n = n0 + ty + 8 * i, k = k0 + tx;
        if (n < N && k < K) {
            fh h, lo;
            cvt_hl(tile[tx][ty + 8 * i], h, lo);
            thp[(size_t)n * K + k] = h;
            tlp[(size_t)n * K + k] = lo;
        }
    }
}

// ---------------- embedding ----------------
__global__ void embed_kernel(const int* __restrict__ idx,
                             const float* __restrict__ tok,
                             const float* __restrict__ pos) {
    int i = blockIdx.x, c = threadIdx.x;
    int t = i % Tt;
    g_x[(size_t)i * Cc + c] = tok[(size_t)idx[i] * Cc + c] + pos[(size_t)t * Cc + c];
}

// ---------------- layernorm -> fp16 ----------------
template <int NW>
__device__ __forceinline__ float blk_sum(float v) {
    __shared__ float sh[NW];
    int lane = threadIdx.x & 31, w = threadIdx.x >> 5;
#pragma unroll
    for (int o = 16; o > 0; o >>= 1) v += __shfl_down_sync(0xffffffffu, v, o);
    if (lane == 0) sh[w] = v;
    __syncthreads();
    if (threadIdx.x == 0) {
        float t = 0.f;
#pragma unroll
        for (int i = 0; i < NW; i++) t += sh[i];
        sh[0] = t;
    }
    __syncthreads();
    float r = sh[0];
    __syncthreads();
    return r;
}

__global__ void ln_h_kernel(const float* __restrict__ in, const float* __restrict__ g,
                            const float* __restrict__ b, fh* __restrict__ oh) {
    int row = blockIdx.x;
    const float* p = in + (size_t)row * Cc;
    int c = threadIdx.x;
    float x0 = p[c], x1 = p[c + 128], x2 = p[c + 256];
    float s = blk_sum<4>(x0 + x1 + x2);
    float mu = s * (1.f / Cc);
    float d0 = x0 - mu, d1 = x1 - mu, d2 = x2 - mu;
    float s2 = blk_sum<4>(d0 * d0 + d1 * d1 + d2 * d2);
    float w = rsqrtf(s2 * (1.f / Cc) + LN_EPS);
    size_t ro = (size_t)row * Cc;
    oh[ro + c]       = __float2half_rn(d0 * w * g[c]       + b[c]);
    oh[ro + c + 128] = __float2half_rn(d1 * w * g[c + 128] + b[c + 128]);
    oh[ro + c + 256] = __float2half_rn(d2 * w * g[c + 256] + b[c + 256]);
}

// ============================================================================
// fp16 single-pass GEMM, 3-stage cp.async pipeline (prefetch depth 2)
// C[M,N] = A[M,K] @ B^T   A plain fp16 [M][K], B^T = Bh [N][K]
// Block 128x128, BK=32, 256 threads, warp tile 64x32, one barrier per tile
// ============================================================================
#define GBM 128
#define GBN 128
#define GBK 32
#define LDS_K 40
#define MAT_H (GBM * LDS_K)             // halves per matrix tile (5120)
#define STAGE_H (2 * MAT_H)             // halves per stage (A + B)
#define STAGE_B (STAGE_H * 2)           // bytes per stage (20480)
#define GEMM_SMEM (3 * STAGE_B)         // 61440

__device__ __forceinline__ void mma16816(float* c, const unsigned* a, const unsigned* b) {
    asm volatile(
        "mma.sync.aligned.m16n8k16.row.col.f32.f16.f16.f32 "
        "{%0,%1,%2,%3}, {%4,%5,%6,%7}, {%8,%9}, {%0,%1,%2,%3};"
        : "+f"(c[0]), "+f"(c[1]), "+f"(c[2]), "+f"(c[3])
        : "r"(a[0]), "r"(a[1]), "r"(a[2]), "r"(a[3]), "r"(b[0]), "r"(b[1]));
}

__device__ __forceinline__ void cpa16(unsigned dst, const void* src, int szn) {
    asm volatile("cp.async.cg.shared.global [%0], [%1], 16, %2;"
                 :: "r"(dst), "l"(src), "r"(szn));
}

template <bool BIAS, bool RELU, bool RES, bool CVT, bool LSE>
__device__ __forceinline__ void bgemm_body(
    const fh* __restrict__ A_g, const fh* __restrict__ Bh_g,
    const float* __restrict__ bias, const float* __restrict__ res,
    float* __restrict__ Cf, fh* __restrict__ Oh,
    int M, int N, int K) {
    extern __shared__ fh sm[];
    unsigned sbase = (unsigned)__cvta_generic_to_shared(sm);

    int tid = threadIdx.x;
    int lane = tid & 31, warp = tid >> 5;
    int wm = warp & 1, wn = warp >> 1;
    int m0 = blockIdx.y * GBM, n0 = blockIdx.x * GBN;
    int g = lane >> 2, tg = lane & 3;

    float acc[4][4][4];
#pragma unroll
    for (int i = 0; i < 4; i++)
#pragma unroll
        for (int j = 0; j < 4; j++)
#pragma unroll
            for (int r = 0; r < 4; r++) acc[i][j][r] = 0.f;

    const int NT = K / GBK;

    auto load_tile = [&](int kt, int st) {
        int k0 = kt * GBK;
        unsigned sb = sbase + st * STAGE_B;
#pragma unroll
        for (int r = 0; r < 2; r++) {
            int cid = tid + r * 256;
            int row = cid >> 2, kch = (cid & 3) * 8;
            unsigned d = sb + (unsigned)(row * LDS_K + kch) * 2;
            size_t aoff = (size_t)(m0 + row) * K + k0 + kch;
            cpa16(d, A_g + aoff, 16);
            int bn = n0 + row;
            int ok = (bn < N) ? 16 : 0;
            size_t boff = (bn < N) ? ((size_t)bn * K + k0 + kch) : 0;
            cpa16(d + (unsigned)(MAT_H * 2), Bh_g + boff, ok);
        }
    };

    load_tile(0, 0);
    asm volatile("cp.async.commit_group;");
    load_tile(1, 1);                       // NT >= 2 always (K >= 64)
    asm volatile("cp.async.commit_group;");

    for (int t = 0; t < NT; t++) {
        if (t + 1 < NT) asm volatile("cp.async.wait_group 1;");
        else            asm volatile("cp.async.wait_group 0;");
        __syncthreads();                   // tile t visible; stage (t+2)%3 free
        if (t + 2 < NT) {
            load_tile(t + 2, (t + 2) % 3);
            asm volatile("cp.async.commit_group;");
        }
        const fh* A_s  = sm + (t % 3) * STAGE_H;
        const fh* Bh_s = A_s + MAT_H;
#pragma unroll
        for (int kc = 0; kc < GBK; kc += 16) {
            unsigned ah[4][4], bh[4][2];
#pragma unroll
            for (int mt = 0; mt < 4; mt++) {
                int r = wm * 64 + mt * 16 + g;
                int base = r * LDS_K + kc + tg * 2;
                ah[mt][0] = *(const unsigned*)&A_s[base];
                ah[mt][1] = *(const unsigned*)&A_s[base + 8 * LDS_K];
                ah[mt][2] = *(const unsigned*)&A_s[base + 8];
                ah[mt][3] = *(const unsigned*)&A_s[base + 8 * LDS_K + 8];
            }
#pragma unroll
            for (int nt = 0; nt < 4; nt++) {
                int n = wn * 32 + nt * 8 + g;
                int base = n * LDS_K + kc + tg * 2;
                bh[nt][0] = *(const unsigned*)&Bh_s[base];
                bh[nt][1] = *(const unsigned*)&Bh_s[base + 8];
            }
#pragma unroll
            for (int mt = 0; mt < 4; mt++)
#pragma unroll
                for (int nt = 0; nt < 4; nt++) mma16816(acc[mt][nt], ah[mt], bh[nt]);
        }
    }
    __syncthreads();

    // epilogue (+ optional fused LSE partials for the LM head)
    float lsm[4][2], lss[4][2];
    if (LSE) {
#pragma unroll
        for (int mt = 0; mt < 4; mt++) {
            lsm[mt][0] = -1e30f; lsm[mt][1] = -1e30f;
            lss[mt][0] = 0.f;    lss[mt][1] = 0.f;
        }
    }
#pragma unroll
    for (int mt = 0; mt < 4; mt++) {
        int r = m0 + wm * 64 + mt * 16 + g;
#pragma unroll
        for (int nt = 0; nt < 4; nt++) {
            int c = n0 + wn * 32 + nt * 8 + tg * 2;
            if (c < N) {
                float v0 = acc[mt][nt][0], v1 = acc[mt][nt][1];
                float v2 = acc[mt][nt][2], v3 = acc[mt][nt][3];
                if (BIAS) { float b0 = bias[c], b1 = bias[c + 1]; v0 += b0; v1 += b1; v2 += b0; v3 += b1; }
                if (RELU) { v0 = fmaxf(v0, 0.f); v1 = fmaxf(v1, 0.f); v2 = fmaxf(v2, 0.f); v3 = fmaxf(v3, 0.f); }
                size_t o0 = (size_t)r * N + c, o1 = (size_t)(r + 8) * N + c;
                if (CVT) {
                    *(fh2*)(Oh + o0) = fh2(__float2half_rn(v0), __float2half_rn(v1));
                    *(fh2*)(Oh + o1) = fh2(__float2half_rn(v2), __float2half_rn(v3));
                } else {
                    if (RES) {
                        float2 r0 = *(const float2*)(res + o0), r1 = *(const float2*)(res + o1);
                        v0 += r0.x; v1 += r0.y; v2 += r1.x; v3 += r1.y;
                    }
                    *(float2*)(Cf + o0) = make_float2(v0, v1);
                    *(float2*)(Cf + o1) = make_float2(v2, v3);
                }
                if (LSE) {
                    lse_up(lsm[mt][0], lss[mt][0], v0);
                    lse_up(lsm[mt][0], lss[mt][0], v1);
                    lse_up(lsm[mt][1], lss[mt][1], v2);
                    lse_up(lsm[mt][1], lss[mt][1], v3);
                }
            }
        }
    }
    if (LSE) {
        __syncthreads();
        float2* part = (float2*)sm;   // [128][4]
#pragma unroll
        for (int mt = 0; mt < 4; mt++)
#pragma unroll
            for (int h2 = 0; h2 < 2; h2++) {
                float m = lsm[mt][h2], s = lss[mt][h2];
#pragma unroll
                for (int o = 1; o <= 2; o <<= 1) {
                    float m2 = __shfl_xor_sync(0xffffffffu, m, o);
                    float s2 = __shfl_xor_sync(0xffffffffu, s, o);
                    lse_merge(m, s, m2, s2);
                }
                if (tg == 0) {
                    int rl = wm * 64 + mt * 16 + g + h2 * 8;
                    part[rl * 4 + wn] = make_float2(m, s);
                }
            }
        __syncthreads();
        if (tid < 128) {
            float m = -1e30f, s = 0.f;
#pragma unroll
            for (int j = 0; j < 4; j++) {
                float2 p = part[tid * 4 + j];
                lse_merge(m, s, p.x, p.y);
            }
            g_lsep[(size_t)(m0 + tid) * NBLK_LM + blockIdx.x] = make_float2(m, s);
        }
    }
}

template <bool BIAS, bool RELU, bool RES, bool CVT, bool LSE>
__global__ void __launch_bounds__(256)
bgemm_kernel(const fh* A, const fh* Bh,
             const float* bias, const float* res, float* Cf, fh* Oh,
             int M, int N, int K) {
    bgemm_body<BIAS, RELU, RES, CVT, LSE>(A, Bh, bias, res, Cf, Oh, M, N, K);
}

// fused qkv via blockIdx.z (single-pass fp16)
__global__ void __launch_bounds__(256)
qkv_kernel(const fh* A, const fh* qh, const fh* kh, const fh* vh,
           float* oq, float* ok, float* ov, int M) {
    const fh* Bh = (blockIdx.z == 0) ? qh : (blockIdx.z == 1) ? kh : vh;
    float* O = (blockIdx.z == 0) ? oq : (blockIdx.z == 1) ? ok : ov;
    bgemm_body<false, false, false, false, false>(A, Bh, nullptr, nullptr, O, nullptr,
                                                  M, Cc, Cc);
}

// ---------------- attention: warp per query, lanes split DH ----------------
__global__ void attn_kernel(const float* __restrict__ q, const float* __restrict__ k,
                            const float* __restrict__ v, fh* __restrict__ oh) {
    extern __shared__ float2 sm2[];
    float2* ks2 = sm2;              // [Tt][32]
    float2* vs2 = sm2 + Tt * 32;
    int b = blockIdx.y, h = blockIdx.x;
    size_t base = (size_t)b * Tt * Cc + (size_t)h * DHh;

    for (int j = threadIdx.x; j < Tt * 32; j += blockDim.x) {
        int s = j >> 5, pair = j & 31;
        ks2[j] = *(const float2*)(k + base + (size_t)s * Cc + pair * 2);
        vs2[j] = *(const float2*)(v + base + (size_t)s * Cc + pair * 2);
    }
    __syncthreads();

    int lane = threadIdx.x & 31, warp = threadIdx.x >> 5;  // 8 warps
    const float scale = 0.125f;

    for (int j = 0; j < 16; j++) {
        int t = warp + 8 * j;
        float2 qv = *(const float2*)(q + base + (size_t)t * Cc + lane * 2);
        float m = -1e30f, ls = 0.f, ax = 0.f, ay = 0.f;
        for (int s = 0; s <= t; s++) {
            float2 kf = ks2[s * 32 + lane];
            float d = qv.x * kf.x + qv.y * kf.y;
#pragma unroll
            for (int o = 16; o > 0; o >>= 1) d += __shfl_xor_sync(0xffffffffu, d, o);
            d *= scale;
            float2 vf = vs2[s * 32 + lane];
            if (d > m) {
                float f = __expf(m - d);
                ls = ls * f + 1.f;
                ax = ax * f + vf.x;
                ay = ay * f + vf.y;
                m = d;
            } else {
                float w = __expf(d - m);
                ls += w;
                ax += w * vf.x;
                ay += w * vf.y;
            }
        }
        float inv = 1.f / ls;
        size_t oo = base + (size_t)t * Cc + lane * 2;
        *(fh2*)(oh + oo) = fh2(__float2half_rn(ax * inv), __float2half_rn(ay * inv));
    }
}

// ---------------- NLL finish from fused LSE partials ----------------
__global__ void nll_finish(const float* __restrict__ logits, const int* __restrict__ tgt) {
    int row = blockIdx.x;
    int lane = threadIdx.x;
    float m = -1e30f, s = 0.f;
    for (int j = lane; j < NBLK_LM; j += 32) {
        float2 p = g_lsep[(size_t)row * NBLK_LM + j];
        lse_merge(m, s, p.x, p.y);
    }
#pragma unroll
    for (int o = 16; o > 0; o >>= 1) {
        float m2 = __shfl_xor_sync(0xffffffffu, m, o);
        float s2 = __shfl_xor_sync(0xffffffffu, s, o);
        lse_merge(m, s, m2, s2);
    }
    if (lane == 0)
        g_nll[row] = -(logits[(size_t)row * Vv + tgt[row]] - m - logf(s));
}

__global__ void loss_kernel(float* __restrict__ out, int M, int write_loss) {
    float s = 0.f;
    for (int i = threadIdx.x; i < M; i += 256) s += g_nll[i];
    int lane = threadIdx.x & 31, w = threadIdx.x >> 5;
#pragma unroll
    for (int o = 16; o > 0; o >>= 1) s += __shfl_down_sync(0xffffffffu, s, o);
    __shared__ float sh[8];
    if (lane == 0) sh[w] = s;
    __syncthreads();
    if (threadIdx.x == 0 && write_loss) {
        float t = 0.f;
#pragma unroll
        for (int i = 0; i < 8; i++) t += sh[i];
        out[(size_t)M * Vv] = t / (float)M;
    }
}

// ---------------- launch ----------------
extern "C" void kernel_launch(void* const* d_in, const int* in_sizes, int n_in,
                              void* d_out, int out_size) {
    const int*   idx  = (const int*)d_in[0];
    const int*   tgt  = (const int*)d_in[1];
    const float* tok  = (const float*)d_in[2];
    const float* pos  = (const float*)d_in[3];
    const float* wq   = (const float*)d_in[4];
    const float* wk   = (const float*)d_in[5];
    const float* wv   = (const float*)d_in[6];
    const float* wo   = (const float*)d_in[7];
    const float* bo   = (const float*)d_in[8];
    const float* ln1g = (const float*)d_in[9];
    const float* ln1b = (const float*)d_in[10];
    const float* ln2g = (const float*)d_in[11];
    const float* ln2b = (const float*)d_in[12];
    const float* w1   = (const float*)d_in[13];
    const float* b1   = (const float*)d_in[14];
    const float* w2   = (const float*)d_in[15];
    const float* b2   = (const float*)d_in[16];
    const float* lnfg = (const float*)d_in[17];
    const float* lnfb = (const float*)d_in[18];
    const float* lmw  = (const float*)d_in[19];
    const float* lmb  = (const float*)d_in[20];
    float* out = (float*)d_out;

    int M  = in_sizes[0];
    int Bb = M / Tt;

    float *x, *q, *k, *v;
    fh *ha, *at, *ff;
    fh *wqh, *wql, *wkh, *wkl, *wvh, *wvl, *woh, *wol;
    fh *w1h, *w1l, *w2h, *w2l, *lmh, *lml;
    cudaGetSymbolAddress((void**)&x, g_x);
    cudaGetSymbolAddress((void**)&q, g_q);
    cudaGetSymbolAddress((void**)&k, g_k);
    cudaGetSymbolAddress((void**)&v, g_v);
    cudaGetSymbolAddress((void**)&ha, g_ha);
    cudaGetSymbolAddress((void**)&at, g_at);
    cudaGetSymbolAddress((void**)&ff, g_ff);
    cudaGetSymbolAddress((void**)&wqh, g_wqh); cudaGetSymbolAddress((void**)&wql, g_wql);
    cudaGetSymbolAddress((void**)&wkh, g_wkh); cudaGetSymbolAddress((void**)&wkl, g_wkl);
    cudaGetSymbolAddress((void**)&wvh, g_wvh); cudaGetSymbolAddress((void**)&wvl, g_wvl);
    cudaGetSymbolAddress((void**)&woh, g_woh); cudaGetSymbolAddress((void**)&wol, g_wol);
    cudaGetSymbolAddress((void**)&w1h, g_w1h); cudaGetSymbolAddress((void**)&w1l, g_w1l);
    cudaGetSymbolAddress((void**)&w2h, g_w2h); cudaGetSymbolAddress((void**)&w2l, g_w2l);
    cudaGetSymbolAddress((void**)&lmh, g_lmh); cudaGetSymbolAddress((void**)&lml, g_lml);

    int attn_smem = 2 * Tt * 32 * (int)sizeof(float2);  // 64 KB
    cudaFuncSetAttribute(attn_kernel, cudaFuncAttributeMaxDynamicSharedMemorySize, attn_smem);
    cudaFuncSetAttribute(qkv_kernel, cudaFuncAttributeMaxDynamicSharedMemorySize, GEMM_SMEM);
    cudaFuncSetAttribute(bgemm_kernel<true, false, true, false, false>,
                         cudaFuncAttributeMaxDynamicSharedMemorySize, GEMM_SMEM);
    cudaFuncSetAttribute(bgemm_kernel<true, true, false, true, false>,
                         cudaFuncAttributeMaxDynamicSharedMemorySize, GEMM_SMEM);
    cudaFuncSetAttribute(bgemm_kernel<true, false, false, false, true>,
                         cudaFuncAttributeMaxDynamicSharedMemorySize, GEMM_SMEM);

    dim3 tb(32, 8);
    dim3 blk(256);

    // ---- launch order: 6th launch (ncu -s 5 -c 1) is the layer-0 qkv GEMM ----
    embed_kernel<<<M, Cc>>>(idx, tok, pos);                               // 1
    wsplit_t<<<dim3(Cc / 32, Cc / 32, Ll), tb>>>(wq, wqh, wql, Cc, Cc);   // 2
    wsplit_t<<<dim3(Cc / 32, Cc / 32, Ll), tb>>>(wk, wkh, wkl, Cc, Cc);   // 3
    wsplit_t<<<dim3(Cc / 32, Cc / 32, Ll), tb>>>(wv, wvh, wvl, Cc, Cc);   // 4
    ln_h_kernel<<<M, 128>>>(x, ln1g, ln1b, ha);                           // 5
    qkv_kernel<<<dim3(Cc / GBN, M / GBM, 3), blk, GEMM_SMEM>>>(           // 6 <- profiled
        ha, wqh, wkh, wvh, q, k, v, M);
    wsplit_t<<<dim3(Cc / 32, Cc / 32, Ll), tb>>>(wo, woh, wol, Cc, Cc);
    wsplit_t<<<dim3(FFf / 32, Cc / 32, Ll), tb>>>(w1, w1h, w1l, Cc, FFf);
    wsplit_t<<<dim3(Cc / 32, FFf / 32, Ll), tb>>>(w2, w2h, w2l, FFf, Cc);
    wsplit_t<<<dim3((Vv + 31) / 32, Cc / 32, 1), tb>>>(lmw, lmh, lml, Cc, Vv);

    for (int l = 0; l < Ll; l++) {
        size_t wofs = (size_t)l * Cc * Cc;
        size_t f1 = (size_t)l * Cc * FFf;
        if (l > 0) {
            ln_h_kernel<<<M, 128>>>(x, ln1g + l * Cc, ln1b + l * Cc, ha);
            qkv_kernel<<<dim3(Cc / GBN, M / GBM, 3), blk, GEMM_SMEM>>>(
                ha, wqh + wofs, wkh + wofs, wvh + wofs, q, k, v, M);
        }
        attn_kernel<<<dim3(Hh, Bb), 256, attn_smem>>>(q, k, v, at);
        bgemm_kernel<true, false, true, false, false><<<dim3(Cc / GBN, M / GBM), blk, GEMM_SMEM>>>(
            at, woh + wofs, bo + l * Cc, x, x, nullptr, M, Cc, Cc);
        ln_h_kernel<<<M, 128>>>(x, ln2g + l * Cc, ln2b + l * Cc, ha);
        bgemm_kernel<true, true, false, true, false><<<dim3(FFf / GBN, M / GBM), blk, GEMM_SMEM>>>(
            ha, w1h + f1, b1 + l * FFf, nullptr, nullptr, ff, M, FFf, Cc);
        bgemm_kernel<true, false, true, false, false><<<dim3(Cc / GBN, M / GBM), blk, GEMM_SMEM>>>(
            ff, w2h + f1, b2 + l * Cc, x, x, nullptr, M, Cc, FFf);
    }

    ln_h_kernel<<<M, 128>>>(x, lnfg, lnfb, ha);
    bgemm_kernel<true, false, false, false, true><<<dim3((Vv + GBN - 1) / GBN, M / GBM), blk, GEMM_SMEM>>>(
        ha, lmh, lmb, nullptr, out, nullptr, M, Vv, Cc);

    nll_finish<<<M, 32>>>(out, tgt);
    int wr = ((long long)out_size > (long long)M * (long long)Vv) ? 1 : 0;
    loss_kernel<<<1, 256>>>(out, M, wr);
}

// round 15
// speedup vs baseline: 1.5034x; 1.5034x over previous
#include <cuda_runtime.h>
#include <cuda_fp16.h>

#define Bsz  64
#define Tt   128
#define Cc   384
#define Hh   6
#define DHh  64
#define Ll   6
#define FFf  1536
#define Vv   25000
#define NTOK (Bsz * Tt)
#define LN_EPS 1e-5f
#define NBLK_LM 196              // ceil(25000/128)

typedef __half fh;
typedef __half2 fh2;

// ---------------- scratch (device globals: allocation-free) ----------------
__device__ float g_x[NTOK * Cc];
__device__ fh    g_q[NTOK * Cc];
__device__ fh    g_k[NTOK * Cc];
__device__ fh    g_v[NTOK * Cc];
__device__ float g_nll[NTOK];
__device__ float2 g_lsep[(size_t)NTOK * NBLK_LM];

// fp16 activations
__device__ fh g_ha[NTOK * Cc];       // LN outputs
__device__ fh g_at[NTOK * Cc];       // attention outputs
__device__ fh g_ff[NTOK * FFf];      // FFN1 outputs

// transposed fp16 weights [N][K]
__device__ fh g_wqh[Ll * Cc * Cc],  g_wql[Ll * Cc * Cc];
__device__ fh g_wkh[Ll * Cc * Cc],  g_wkl[Ll * Cc * Cc];
__device__ fh g_wvh[Ll * Cc * Cc],  g_wvl[Ll * Cc * Cc];
__device__ fh g_woh[Ll * Cc * Cc],  g_wol[Ll * Cc * Cc];
__device__ fh g_w1h[Ll * Cc * FFf], g_w1l[Ll * Cc * FFf];
__device__ fh g_w2h[Ll * FFf * Cc], g_w2l[Ll * FFf * Cc];
__device__ fh g_lmh[(size_t)Vv * Cc], g_lml[(size_t)Vv * Cc];

__device__ __forceinline__ void cvt_hl(float x, fh& h, fh& l) {
    h = __float2half_rn(x);
    l = __float2half_rn(x - __half2float(h));
}

__device__ __forceinline__ void lse_up(float& m, float& s, float v) {
    if (v > m) { s = s * __expf(m - v) + 1.f; m = v; }
    else       { s += __expf(v - m); }
}
__device__ __forceinline__ void lse_merge(float& m, float& s, float m2, float s2) {
    float nm = fmaxf(m, m2);
    s = s * __expf(m - nm) + s2 * __expf(m2 - nm);
    m = nm;
}

// ---------------- weight transpose + split: w[K][N] -> th/tl[N][K] ---------
__global__ void wsplit_t(const float* __restrict__ w, fh* __restrict__ th,
                         fh* __restrict__ tl, int K, int N) {
    __shared__ float tile[32][33];
    int l = blockIdx.z;
    const float* wp = w + (size_t)l * K * N;
    fh* thp = th + (size_t)l * K * N;
    fh* tlp = tl + (size_t)l * K * N;
    int n0 = blockIdx.x * 32, k0 = blockIdx.y * 32;
    int tx = threadIdx.x, ty = threadIdx.y;  // 32 x 8
#pragma unroll
    for (int i = 0; i < 4; i++) {
        int k = k0 + ty + 8 * i, n = n0 + tx;
        tile[ty + 8 * i][tx] = (k < K && n < N) ? wp[(size_t)k * N + n] : 0.f;
    }
    __syncthreads();
#pragma unroll
    for (int i = 0; i < 4; i++) {
        int n = n0 + ty + 8 * i, k = k0 + tx;
        if (n < N && k < K) {
            fh h, lo;
            cvt_hl(tile[tx][ty + 8 * i], h, lo);
            thp[(size_t)n * K + k] = h;
            tlp[(size_t)n * K + k] = lo;
        }
    }
}

// ---------------- embedding ----------------
__global__ void embed_kernel(const int* __restrict__ idx,
                             const float* __restrict__ tok,
                             const float* __restrict__ pos) {
    int i = blockIdx.x, c = threadIdx.x;
    int t = i % Tt;
    g_x[(size_t)i * Cc + c] = tok[(size_t)idx[i] * Cc + c] + pos[(size_t)t * Cc + c];
}

// ---------------- layernorm -> fp16 ----------------
template <int NW>
__device__ __forceinline__ float blk_sum(float v) {
    __shared__ float sh[NW];
    int lane = threadIdx.x & 31, w = threadIdx.x >> 5;
#pragma unroll
    for (int o = 16; o > 0; o >>= 1) v += __shfl_down_sync(0xffffffffu, v, o);
    if (lane == 0) sh[w] = v;
    __syncthreads();
    if (threadIdx.x == 0) {
        float t = 0.f;
#pragma unroll
        for (int i = 0; i < NW; i++) t += sh[i];
        sh[0] = t;
    }
    __syncthreads();
    float r = sh[0];
    __syncthreads();
    return r;
}

__global__ void ln_h_kernel(const float* __restrict__ in, const float* __restrict__ g,
                            const float* __restrict__ b, fh* __restrict__ oh) {
    int row = blockIdx.x;
    const float* p = in + (size_t)row * Cc;
    int c = threadIdx.x;
    float x0 = p[c], x1 = p[c + 128], x2 = p[c + 256];
    float s = blk_sum<4>(x0 + x1 + x2);
    float mu = s * (1.f / Cc);
    float d0 = x0 - mu, d1 = x1 - mu, d2 = x2 - mu;
    float s2 = blk_sum<4>(d0 * d0 + d1 * d1 + d2 * d2);
    float w = rsqrtf(s2 * (1.f / Cc) + LN_EPS);
    size_t ro = (size_t)row * Cc;
    oh[ro + c]       = __float2half_rn(d0 * w * g[c]       + b[c]);
    oh[ro + c + 128] = __float2half_rn(d1 * w * g[c + 128] + b[c + 128]);
    oh[ro + c + 256] = __float2half_rn(d2 * w * g[c + 256] + b[c + 256]);
}

// ============================================================================
// fp16 single-pass GEMM, 2-stage cp.async pipeline (R12 champion mainloop)
// C[M,N] = A[M,K] @ B^T   A plain fp16 [M][K], B^T = Bh [N][K]
// Block 128x128, BK=32, 256 threads, warp tile 64x32
// ============================================================================
#define GBM 128
#define GBN 128
#define GBK 32
#define LDS_K 40
#define MAT_H (GBM * LDS_K)             // halves per matrix tile (5120)
#define STAGE_H (2 * MAT_H)             // halves per stage (A + B)
#define STAGE_B (STAGE_H * 2)           // bytes per stage (20480)
#define GEMM_SMEM (2 * STAGE_B)         // 40960

__device__ __forceinline__ void mma16816(float* c, const unsigned* a, const unsigned* b) {
    asm volatile(
        "mma.sync.aligned.m16n8k16.row.col.f32.f16.f16.f32 "
        "{%0,%1,%2,%3}, {%4,%5,%6,%7}, {%8,%9}, {%0,%1,%2,%3};"
        : "+f"(c[0]), "+f"(c[1]), "+f"(c[2]), "+f"(c[3])
        : "r"(a[0]), "r"(a[1]), "r"(a[2]), "r"(a[3]), "r"(b[0]), "r"(b[1]));
}

__device__ __forceinline__ void cpa16(unsigned dst, const void* src, int szn) {
    asm volatile("cp.async.cg.shared.global [%0], [%1], 16, %2;"
                 :: "r"(dst), "l"(src), "r"(szn));
}

template <bool BIAS, bool RELU, bool RES, bool CVT, bool LSE>
__device__ __forceinline__ void bgemm_body(
    const fh* __restrict__ A_g, const fh* __restrict__ Bh_g,
    const float* __restrict__ bias, const float* __restrict__ res,
    float* __restrict__ Cf, fh* __restrict__ Oh,
    int M, int N, int K) {
    extern __shared__ fh sm[];
    unsigned sbase = (unsigned)__cvta_generic_to_shared(sm);

    int tid = threadIdx.x;
    int lane = tid & 31, warp = tid >> 5;
    int wm = warp & 1, wn = warp >> 1;
    int m0 = blockIdx.y * GBM, n0 = blockIdx.x * GBN;
    int g = lane >> 2, tg = lane & 3;

    float acc[4][4][4];
#pragma unroll
    for (int i = 0; i < 4; i++)
#pragma unroll
        for (int j = 0; j < 4; j++)
#pragma unroll
            for (int r = 0; r < 4; r++) acc[i][j][r] = 0.f;

    const int NT = K / GBK;

    auto load_tile = [&](int kt, int st) {
        int k0 = kt * GBK;
        unsigned sb = sbase + st * STAGE_B;
#pragma unroll
        for (int r = 0; r < 2; r++) {
            int cid = tid + r * 256;
            int row = cid >> 2, kch = (cid & 3) * 8;
            unsigned d = sb + (unsigned)(row * LDS_K + kch) * 2;
            size_t aoff = (size_t)(m0 + row) * K + k0 + kch;
            cpa16(d, A_g + aoff, 16);
            int bn = n0 + row;
            int ok = (bn < N) ? 16 : 0;
            size_t boff = (bn < N) ? ((size_t)bn * K + k0 + kch) : 0;
            cpa16(d + (unsigned)(MAT_H * 2), Bh_g + boff, ok);
        }
    };

    load_tile(0, 0);
    asm volatile("cp.async.commit_group;");

    for (int t = 0; t < NT; t++) {
        asm volatile("cp.async.wait_group 0;");
        __syncthreads();
        if (t + 1 < NT) {
            load_tile(t + 1, (t + 1) & 1);
            asm volatile("cp.async.commit_group;");
        }
        const fh* A_s  = sm + (t & 1) * STAGE_H;
        const fh* Bh_s = A_s + MAT_H;
#pragma unroll
        for (int kc = 0; kc < GBK; kc += 16) {
            unsigned ah[4][4], bh[4][2];
#pragma unroll
            for (int mt = 0; mt < 4; mt++) {
                int r = wm * 64 + mt * 16 + g;
                int base = r * LDS_K + kc + tg * 2;
                ah[mt][0] = *(const unsigned*)&A_s[base];
                ah[mt][1] = *(const unsigned*)&A_s[base + 8 * LDS_K];
                ah[mt][2] = *(const unsigned*)&A_s[base + 8];
                ah[mt][3] = *(const unsigned*)&A_s[base + 8 * LDS_K + 8];
            }
#pragma unroll
            for (int nt = 0; nt < 4; nt++) {
                int n = wn * 32 + nt * 8 + g;
                int base = n * LDS_K + kc + tg * 2;
                bh[nt][0] = *(const unsigned*)&Bh_s[base];
                bh[nt][1] = *(const unsigned*)&Bh_s[base + 8];
            }
#pragma unroll
            for (int mt = 0; mt < 4; mt++)
#pragma unroll
                for (int nt = 0; nt < 4; nt++) mma16816(acc[mt][nt], ah[mt], bh[nt]);
        }
        __syncthreads();
    }

    // epilogue (+ optional fused LSE partials for the LM head)
    float lsm[4][2], lss[4][2];
    if (LSE) {
#pragma unroll
        for (int mt = 0; mt < 4; mt++) {
            lsm[mt][0] = -1e30f; lsm[mt][1] = -1e30f;
            lss[mt][0] = 0.f;    lss[mt][1] = 0.f;
        }
    }
#pragma unroll
    for (int mt = 0; mt < 4; mt++) {
        int r = m0 + wm * 64 + mt * 16 + g;
#pragma unroll
        for (int nt = 0; nt < 4; nt++) {
            int c = n0 + wn * 32 + nt * 8 + tg * 2;
            if (c < N) {
                float v0 = acc[mt][nt][0], v1 = acc[mt][nt][1];
                float v2 = acc[mt][nt][2], v3 = acc[mt][nt][3];
                if (BIAS) { float b0 = bias[c], b1 = bias[c + 1]; v0 += b0; v1 += b1; v2 += b0; v3 += b1; }
                if (RELU) { v0 = fmaxf(v0, 0.f); v1 = fmaxf(v1, 0.f); v2 = fmaxf(v2, 0.f); v3 = fmaxf(v3, 0.f); }
                size_t o0 = (size_t)r * N + c, o1 = (size_t)(r + 8) * N + c;
                if (CVT) {
                    *(fh2*)(Oh + o0) = fh2(__float2half_rn(v0), __float2half_rn(v1));
                    *(fh2*)(Oh + o1) = fh2(__float2half_rn(v2), __float2half_rn(v3));
                } else {
                    if (RES) {
                        float2 r0 = *(const float2*)(res + o0), r1 = *(const float2*)(res + o1);
                        v0 += r0.x; v1 += r0.y; v2 += r1.x; v3 += r1.y;
                    }
                    *(float2*)(Cf + o0) = make_float2(v0, v1);
                    *(float2*)(Cf + o1) = make_float2(v2, v3);
                }
                if (LSE) {
                    lse_up(lsm[mt][0], lss[mt][0], v0);
                    lse_up(lsm[mt][0], lss[mt][0], v1);
                    lse_up(lsm[mt][1], lss[mt][1], v2);
                    lse_up(lsm[mt][1], lss[mt][1], v3);
                }
            }
        }
    }
    if (LSE) {
        __syncthreads();
        float2* part = (float2*)sm;   // [128][4]
#pragma unroll
        for (int mt = 0; mt < 4; mt++)
#pragma unroll
            for (int h2 = 0; h2 < 2; h2++) {
                float m = lsm[mt][h2], s = lss[mt][h2];
#pragma unroll
                for (int o = 1; o <= 2; o <<= 1) {
                    float m2 = __shfl_xor_sync(0xffffffffu, m, o);
                    float s2 = __shfl_xor_sync(0xffffffffu, s, o);
                    lse_merge(m, s, m2, s2);
                }
                if (tg == 0) {
                    int rl = wm * 64 + mt * 16 + g + h2 * 8;
                    part[rl * 4 + wn] = make_float2(m, s);
                }
            }
        __syncthreads();
        if (tid < 128) {
            float m = -1e30f, s = 0.f;
#pragma unroll
            for (int j = 0; j < 4; j++) {
                float2 p = part[tid * 4 + j];
                lse_merge(m, s, p.x, p.y);
            }
            g_lsep[(size_t)(m0 + tid) * NBLK_LM + blockIdx.x] = make_float2(m, s);
        }
    }
}

template <bool BIAS, bool RELU, bool RES, bool CVT, bool LSE>
__global__ void __launch_bounds__(256)
bgemm_kernel(const fh* A, const fh* Bh,
             const float* bias, const float* res, float* Cf, fh* Oh,
             int M, int N, int K) {
    bgemm_body<BIAS, RELU, RES, CVT, LSE>(A, Bh, bias, res, Cf, Oh, M, N, K);
}

// fused qkv via blockIdx.z: outputs fp16 q/k/v directly (CVT epilogue)
__global__ void __launch_bounds__(256)
qkv_kernel(const fh* A, const fh* qh, const fh* kh, const fh* vh,
           fh* oq, fh* ok, fh* ov, int M) {
    const fh* Bh = (blockIdx.z == 0) ? qh : (blockIdx.z == 1) ? kh : vh;
    fh* O = (blockIdx.z == 0) ? oq : (blockIdx.z == 1) ? ok : ov;
    bgemm_body<false, false, false, true, false>(A, Bh, nullptr, nullptr, nullptr, O,
                                                 M, Cc, Cc);
}

// ============================================================================
// Flash attention on HMMA fragments. One block per (b,h), 128 threads (4 warps).
// Warp w owns query rows [32w, 32w+32). Q,K staged [128][72] fh; V transposed
// [64][136] fh. Online softmax on C-fragments (quad shfl); P fragments reuse
// the C->A layout identity for the P@V mma.
// ============================================================================
#define AQK_LD 72
#define AVT_LD 136
#define ATT_SMEM ((2 * 128 * AQK_LD + 64 * AVT_LD) * 2)   // 54272 bytes

__global__ void __launch_bounds__(128)
attn_kernel(const fh* __restrict__ qg, const fh* __restrict__ kg,
            const fh* __restrict__ vg, fh* __restrict__ og) {
    extern __shared__ fh asm_[];
    fh* qs  = asm_;
    fh* ks  = asm_ + 128 * AQK_LD;
    fh* vts = asm_ + 2 * 128 * AQK_LD;
    int b = blockIdx.y, h = blockIdx.x;
    size_t base = (size_t)b * Tt * Cc + (size_t)h * DHh;
    int tid = threadIdx.x;

    // stage Q, K: 128 rows x 64 fh, uint4 (8 fh) chunks
    for (int i = tid; i < 128 * 8; i += 128) {
        int row = i >> 3, c8 = (i & 7) * 8;
        *(uint4*)&qs[row * AQK_LD + c8] = *(const uint4*)(qg + base + (size_t)row * Cc + c8);
        *(uint4*)&ks[row * AQK_LD + c8] = *(const uint4*)(kg + base + (size_t)row * Cc + c8);
    }
    // stage V transposed: vts[d][s]
    for (int i = tid; i < 128 * 32; i += 128) {
        int s = i >> 5, dp = (i & 31) * 2;
        fh2 vv = *(const fh2*)(vg + base + (size_t)s * Cc + dp);
        vts[dp * AVT_LD + s]       = vv.x;
        vts[(dp + 1) * AVT_LD + s] = vv.y;
    }
    __syncthreads();

    int lane = tid & 31, w = tid >> 5;
    int g = lane >> 2, tg = lane & 3;
    const float scale = 0.125f;

    // Q fragments (held for the whole block): [kc4][mt][4]
    unsigned qa[4][2][4];
#pragma unroll
    for (int kc4 = 0; kc4 < 4; kc4++)
#pragma unroll
        for (int mt = 0; mt < 2; mt++) {
            int r0 = w * 32 + mt * 16 + g;
            int cb = kc4 * 16 + tg * 2;
            qa[kc4][mt][0] = *(const unsigned*)&qs[r0 * AQK_LD + cb];
            qa[kc4][mt][1] = *(const unsigned*)&qs[(r0 + 8) * AQK_LD + cb];
            qa[kc4][mt][2] = *(const unsigned*)&qs[r0 * AQK_LD + cb + 8];
            qa[kc4][mt][3] = *(const unsigned*)&qs[(r0 + 8) * AQK_LD + cb + 8];
        }

    float oacc[2][8][4];
#pragma unroll
    for (int mt = 0; mt < 2; mt++)
#pragma unroll
        for (int dt = 0; dt < 8; dt++)
#pragma unroll
            for (int r = 0; r < 4; r++) oacc[mt][dt][r] = 0.f;
    float mrow[2][2] = {{-1e30f, -1e30f}, {-1e30f, -1e30f}};
    float lrow[2][2] = {{0.f, 0.f}, {0.f, 0.f}};

    int nit = 2 * w + 2;   // s-chunks needed for rows < 32w+32 (warp-uniform)
    for (int it = 0; it < nit; it++) {
        // --- S fragments: 2 mt x 2 snt, accumulate over 4 k-tiles ---
        float sfr[2][2][4];
#pragma unroll
        for (int mt = 0; mt < 2; mt++)
#pragma unroll
            for (int snt = 0; snt < 2; snt++) {
#pragma unroll
                for (int r = 0; r < 4; r++) sfr[mt][snt][r] = 0.f;
                int srow = it * 16 + snt * 8 + g;
#pragma unroll
                for (int kc4 = 0; kc4 < 4; kc4++) {
                    unsigned bb[2];
                    int cb = kc4 * 16 + tg * 2;
                    bb[0] = *(const unsigned*)&ks[srow * AQK_LD + cb];
                    bb[1] = *(const unsigned*)&ks[srow * AQK_LD + cb + 8];
                    mma16816(sfr[mt][snt], qa[kc4][mt], bb);
                }
            }
        // --- online softmax per mt, build P fragments, P@V mma ---
#pragma unroll
        for (int mt = 0; mt < 2; mt++) {
            float pp[2][4];
#pragma unroll
            for (int hf = 0; hf < 2; hf++) {
                int trow = w * 32 + mt * 16 + g + hf * 8;
                int c0 = it * 16 + tg * 2;
                int c2 = it * 16 + 8 + tg * 2;
                float v0 = sfr[mt][0][hf * 2] * scale;
                float v1 = sfr[mt][0][hf * 2 + 1] * scale;
                float v2 = sfr[mt][1][hf * 2] * scale;
                float v3 = sfr[mt][1][hf * 2 + 1] * scale;
                if (c0 > trow)     v0 = -1e30f;
                if (c0 + 1 > trow) v1 = -1e30f;
                if (c2 > trow)     v2 = -1e30f;
                if (c2 + 1 > trow) v3 = -1e30f;
                float cm = fmaxf(fmaxf(v0, v1), fmaxf(v2, v3));
                cm = fmaxf(cm, __shfl_xor_sync(0xffffffffu, cm, 1));
                cm = fmaxf(cm, __shfl_xor_sync(0xffffffffu, cm, 2));
                float mo = mrow[mt][hf];
                float mn = fmaxf(mo, cm);
                float f = __expf(mo - mn);
                float p0 = __expf(v0 - mn), p1 = __expf(v1 - mn);
                float p2 = __expf(v2 - mn), p3 = __expf(v3 - mn);
                float ps = p0 + p1 + p2 + p3;
                ps += __shfl_xor_sync(0xffffffffu, ps, 1);
                ps += __shfl_xor_sync(0xffffffffu, ps, 2);
                lrow[mt][hf] = lrow[mt][hf] * f + ps;
                mrow[mt][hf] = mn;
#pragma unroll
                for (int dt = 0; dt < 8; dt++) {
                    oacc[mt][dt][hf * 2]     *= f;
                    oacc[mt][dt][hf * 2 + 1] *= f;
                }
                pp[hf][0] = p0; pp[hf][1] = p1; pp[hf][2] = p2; pp[hf][3] = p3;
            }
            // C->A fragment identity: pack P into one k16 A fragment
            unsigned pa[4];
            {
                fh2 t0 = fh2(__float2half_rn(pp[0][0]), __float2half_rn(pp[0][1]));
                fh2 t1 = fh2(__float2half_rn(pp[1][0]), __float2half_rn(pp[1][1]));
                fh2 t2 = fh2(__float2half_rn(pp[0][2]), __float2half_rn(pp[0][3]));
                fh2 t3 = fh2(__float2half_rn(pp[1][2]), __float2half_rn(pp[1][3]));
                pa[0] = *(unsigned*)&t0; pa[1] = *(unsigned*)&t1;
                pa[2] = *(unsigned*)&t2; pa[3] = *(unsigned*)&t3;
            }
#pragma unroll
            for (int dt = 0; dt < 8; dt++) {
                unsigned bb[2];
                int vrow = dt * 8 + g;
                int sb = it * 16 + tg * 2;
                bb[0] = *(const unsigned*)&vts[vrow * AVT_LD + sb];
                bb[1] = *(const unsigned*)&vts[vrow * AVT_LD + sb + 8];
                mma16816(oacc[mt][dt], pa, bb);
            }
        }
    }

    // normalize + write (fh2, coalesced within quads)
#pragma unroll
    for (int mt = 0; mt < 2; mt++)
#pragma unroll
        for (int hf = 0; hf < 2; hf++) {
            float inv = 1.f / lrow[mt][hf];
            int row = w * 32 + mt * 16 + g + hf * 8;
#pragma unroll
            for (int dt = 0; dt < 8; dt++) {
                fh2 o = fh2(__float2half_rn(oacc[mt][dt][hf * 2] * inv),
                            __float2half_rn(oacc[mt][dt][hf * 2 + 1] * inv));
                *(fh2*)(og + base + (size_t)row * Cc + dt * 8 + tg * 2) = o;
            }
        }
}

// ---------------- NLL finish from fused LSE partials ----------------
__global__ void nll_finish(const float* __restrict__ logits, const int* __restrict__ tgt) {
    int row = blockIdx.x;
    int lane = threadIdx.x;
    float m = -1e30f, s = 0.f;
    for (int j = lane; j < NBLK_LM; j += 32) {
        float2 p = g_lsep[(size_t)row * NBLK_LM + j];
        lse_merge(m, s, p.x, p.y);
    }
#pragma unroll
    for (int o = 16; o > 0; o >>= 1) {
        float m2 = __shfl_xor_sync(0xffffffffu, m, o);
        float s2 = __shfl_xor_sync(0xffffffffu, s, o);
        lse_merge(m, s, m2, s2);
    }
    if (lane == 0)
        g_nll[row] = -(logits[(size_t)row * Vv + tgt[row]] - m - logf(s));
}

__global__ void loss_kernel(float* __restrict__ out, int M, int write_loss) {
    float s = 0.f;
    for (int i = threadIdx.x; i < M; i += 256) s += g_nll[i];
    int lane = threadIdx.x & 31, w = threadIdx.x >> 5;
#pragma unroll
    for (int o = 16; o > 0; o >>= 1) s += __shfl_down_sync(0xffffffffu, s, o);
    __shared__ float sh[8];
    if (lane == 0) sh[w] = s;
    __syncthreads();
    if (threadIdx.x == 0 && write_loss) {
        float t = 0.f;
#pragma unroll
        for (int i = 0; i < 8; i++) t += sh[i];
        out[(size_t)M * Vv] = t / (float)M;
    }
}

// ---------------- launch ----------------
extern "C" void kernel_launch(void* const* d_in, const int* in_sizes, int n_in,
                              void* d_out, int out_size) {
    const int*   idx  = (const int*)d_in[0];
    const int*   tgt  = (const int*)d_in[1];
    const float* tok  = (const float*)d_in[2];
    const float* pos  = (const float*)d_in[3];
    const float* wq   = (const float*)d_in[4];
    const float* wk   = (const float*)d_in[5];
    const float* wv   = (const float*)d_in[6];
    const float* wo   = (const float*)d_in[7];
    const float* bo   = (const float*)d_in[8];
    const float* ln1g = (const float*)d_in[9];
    const float* ln1b = (const float*)d_in[10];
    const float* ln2g = (const float*)d_in[11];
    const float* ln2b = (const float*)d_in[12];
    const float* w1   = (const float*)d_in[13];
    const float* b1   = (const float*)d_in[14];
    const float* w2   = (const float*)d_in[15];
    const float* b2   = (const float*)d_in[16];
    const float* lnfg = (const float*)d_in[17];
    const float* lnfb = (const float*)d_in[18];
    const float* lmw  = (const float*)d_in[19];
    const float* lmb  = (const float*)d_in[20];
    float* out = (float*)d_out;

    int M  = in_sizes[0];
    int Bb = M / Tt;

    float* x;
    fh *q, *k, *v;
    fh *ha, *at, *ff;
    fh *wqh, *wql, *wkh, *wkl, *wvh, *wvl, *woh, *wol;
    fh *w1h, *w1l, *w2h, *w2l, *lmh, *lml;
    cudaGetSymbolAddress((void**)&x, g_x);
    cudaGetSymbolAddress((void**)&q, g_q);
    cudaGetSymbolAddress((void**)&k, g_k);
    cudaGetSymbolAddress((void**)&v, g_v);
    cudaGetSymbolAddress((void**)&ha, g_ha);
    cudaGetSymbolAddress((void**)&at, g_at);
    cudaGetSymbolAddress((void**)&ff, g_ff);
    cudaGetSymbolAddress((void**)&wqh, g_wqh); cudaGetSymbolAddress((void**)&wql, g_wql);
    cudaGetSymbolAddress((void**)&wkh, g_wkh); cudaGetSymbolAddress((void**)&wkl, g_wkl);
    cudaGetSymbolAddress((void**)&wvh, g_wvh); cudaGetSymbolAddress((void**)&wvl, g_wvl);
    cudaGetSymbolAddress((void**)&woh, g_woh); cudaGetSymbolAddress((void**)&wol, g_wol);
    cudaGetSymbolAddress((void**)&w1h, g_w1h); cudaGetSymbolAddress((void**)&w1l, g_w1l);
    cudaGetSymbolAddress((void**)&w2h, g_w2h); cudaGetSymbolAddress((void**)&w2l, g_w2l);
    cudaGetSymbolAddress((void**)&lmh, g_lmh); cudaGetSymbolAddress((void**)&lml, g_lml);

    cudaFuncSetAttribute(attn_kernel, cudaFuncAttributeMaxDynamicSharedMemorySize, ATT_SMEM);
    cudaFuncSetAttribute(qkv_kernel, cudaFuncAttributeMaxDynamicSharedMemorySize, GEMM_SMEM);
    cudaFuncSetAttribute(bgemm_kernel<true, false, true, false, false>,
                         cudaFuncAttributeMaxDynamicSharedMemorySize, GEMM_SMEM);
    cudaFuncSetAttribute(bgemm_kernel<true, true, false, true, false>,
                         cudaFuncAttributeMaxDynamicSharedMemorySize, GEMM_SMEM);
    cudaFuncSetAttribute(bgemm_kernel<true, false, false, false, true>,
                         cudaFuncAttributeMaxDynamicSharedMemorySize, GEMM_SMEM);

    dim3 tb(32, 8);
    dim3 blk(256);

    // ---- launch order: 6th launch (ncu -s 5 -c 1) is the layer-0 qkv GEMM ----
    embed_kernel<<<M, Cc>>>(idx, tok, pos);                               // 1
    wsplit_t<<<dim3(Cc / 32, Cc / 32, Ll), tb>>>(wq, wqh, wql, Cc, Cc);   // 2
    wsplit_t<<<dim3(Cc / 32, Cc / 32, Ll), tb>>>(wk, wkh, wkl, Cc, Cc);   // 3
    wsplit_t<<<dim3(Cc / 32, Cc / 32, Ll), tb>>>(wv, wvh, wvl, Cc, Cc);   // 4
    ln_h_kernel<<<M, 128>>>(x, ln1g, ln1b, ha);                           // 5
    qkv_kernel<<<dim3(Cc / GBN, M / GBM, 3), blk, GEMM_SMEM>>>(           // 6 <- profiled
        ha, wqh, wkh, wvh, q, k, v, M);
    wsplit_t<<<dim3(Cc / 32, Cc / 32, Ll), tb>>>(wo, woh, wol, Cc, Cc);
    wsplit_t<<<dim3(FFf / 32, Cc / 32, Ll), tb>>>(w1, w1h, w1l, Cc, FFf);
    wsplit_t<<<dim3(Cc / 32, FFf / 32, Ll), tb>>>(w2, w2h, w2l, FFf, Cc);
    wsplit_t<<<dim3((Vv + 31) / 32, Cc / 32, 1), tb>>>(lmw, lmh, lml, Cc, Vv);

    for (int l = 0; l < Ll; l++) {
        size_t wofs = (size_t)l * Cc * Cc;
        size_t f1 = (size_t)l * Cc * FFf;
        if (l > 0) {
            ln_h_kernel<<<M, 128>>>(x, ln1g + l * Cc, ln1b + l * Cc, ha);
            qkv_kernel<<<dim3(Cc / GBN, M / GBM, 3), blk, GEMM_SMEM>>>(
                ha, wqh + wofs, wkh + wofs, wvh + wofs, q, k, v, M);
        }
        attn_kernel<<<dim3(Hh, Bb), 128, ATT_SMEM>>>(q, k, v, at);
        bgemm_kernel<true, false, true, false, false><<<dim3(Cc / GBN, M / GBM), blk, GEMM_SMEM>>>(
            at, woh + wofs, bo + l * Cc, x, x, nullptr, M, Cc, Cc);
        ln_h_kernel<<<M, 128>>>(x, ln2g + l * Cc, ln2b + l * Cc, ha);
        bgemm_kernel<true, true, false, true, false><<<dim3(FFf / GBN, M / GBM), blk, GEMM_SMEM>>>(
            ha, w1h + f1, b1 + l * FFf, nullptr, nullptr, ff, M, FFf, Cc);
        bgemm_kernel<true, false, true, false, false><<<dim3(Cc / GBN, M / GBM), blk, GEMM_SMEM>>>(
            ff, w2h + f1, b2 + l * Cc, x, x, nullptr, M, Cc, FFf);
    }

    ln_h_kernel<<<M, 128>>>(x, lnfg, lnfb, ha);
    bgemm_kernel<true, false, false, false, true><<<dim3((Vv + GBN - 1) / GBN, M / GBM), blk, GEMM_SMEM>>>(
        ha, lmh, lmb, nullptr, out, nullptr, M, Vv, Cc);

    nll_finish<<<M, 32>>>(out, tgt);
    int wr = ((long long)out_size > (long long)M * (long long)Vv) ? 1 : 0;
    loss_kernel<<<1, 256>>>(out, M, wr);
}

// round 16
// speedup vs baseline: 1.5116x; 1.0054x over previous
#include <cuda_runtime.h>
#include <cuda_fp16.h>

#define Bsz  64
#define Tt   128
#define Cc   384
#define Hh   6
#define DHh  64
#define Ll   6
#define FFf  1536
#define Vv   25000
#define NTOK (Bsz * Tt)
#define LN_EPS 1e-5f
#define NBLK_LM 196              // ceil(25000/128)

typedef __half fh;
typedef __half2 fh2;

// ---------------- scratch (device globals: allocation-free) ----------------
__device__ float g_x[NTOK * Cc];
__device__ fh    g_q[NTOK * Cc];
__device__ fh    g_k[NTOK * Cc];
__device__ fh    g_v[NTOK * Cc];
__device__ float g_nll[NTOK];
__device__ float2 g_lsep[(size_t)NTOK * NBLK_LM];

// fp16 activations
__device__ fh g_ha[NTOK * Cc];       // LN outputs
__device__ fh g_at[NTOK * Cc];       // attention outputs
__device__ fh g_ff[NTOK * FFf];      // FFN1 outputs

// transposed fp16 weights [N][K]
__device__ fh g_wqh[Ll * Cc * Cc];
__device__ fh g_wkh[Ll * Cc * Cc];
__device__ fh g_wvh[Ll * Cc * Cc];
__device__ fh g_woh[Ll * Cc * Cc];
__device__ fh g_w1h[Ll * Cc * FFf];
__device__ fh g_w2h[Ll * FFf * Cc];
__device__ fh g_lmh[(size_t)Vv * Cc];

__device__ __forceinline__ void lse_up(float& m, float& s, float v) {
    if (v > m) { s = s * __expf(m - v) + 1.f; m = v; }
    else       { s += __expf(v - m); }
}
__device__ __forceinline__ void lse_merge(float& m, float& s, float m2, float s2) {
    float nm = fmaxf(m, m2);
    s = s * __expf(m - nm) + s2 * __expf(m2 - nm);
    m = nm;
}

// ---------------- weight transpose: w[K][N] -> th[N][K] fp16 (hi only) -----
__global__ void wsplit_t(const float* __restrict__ w, fh* __restrict__ th,
                         int K, int N) {
    __shared__ float tile[32][33];
    int l = blockIdx.z;
    const float* wp = w + (size_t)l * K * N;
    fh* thp = th + (size_t)l * K * N;
    int n0 = blockIdx.x * 32, k0 = blockIdx.y * 32;
    int tx = threadIdx.x, ty = threadIdx.y;  // 32 x 8
#pragma unroll
    for (int i = 0; i < 4; i++) {
        int k = k0 + ty + 8 * i, n = n0 + tx;
        tile[ty + 8 * i][tx] = (k < K && n < N) ? wp[(size_t)k * N + n] : 0.f;
    }
    __syncthreads();
#pragma unroll
    for (int i = 0; i < 4; i++) {
        int n = n0 + ty + 8 * i, k = k0 + tx;
        if (n < N && k < K)
            thp[(size_t)n * K + k] = __float2half_rn(tile[tx][ty + 8 * i]);
    }
}

// ---------------- embedding ----------------
__global__ void embed_kernel(const int* __restrict__ idx,
                             const float* __restrict__ tok,
                             const float* __restrict__ pos) {
    int i = blockIdx.x, c = threadIdx.x;
    int t = i % Tt;
    g_x[(size_t)i * Cc + c] = tok[(size_t)idx[i] * Cc + c] + pos[(size_t)t * Cc + c];
}

// ---------------- layernorm -> fp16 ----------------
template <int NW>
__device__ __forceinline__ float blk_sum(float v) {
    __shared__ float sh[NW];
    int lane = threadIdx.x & 31, w = threadIdx.x >> 5;
#pragma unroll
    for (int o = 16; o > 0; o >>= 1) v += __shfl_down_sync(0xffffffffu, v, o);
    if (lane == 0) sh[w] = v;
    __syncthreads();
    if (threadIdx.x == 0) {
        float t = 0.f;
#pragma unroll
        for (int i = 0; i < NW; i++) t += sh[i];
        sh[0] = t;
    }
    __syncthreads();
    float r = sh[0];
    __syncthreads();
    return r;
}

__global__ void ln_h_kernel(const float* __restrict__ in, const float* __restrict__ g,
                            const float* __restrict__ b, fh* __restrict__ oh) {
    int row = blockIdx.x;
    const float* p = in + (size_t)row * Cc;
    int c = threadIdx.x;
    float x0 = p[c], x1 = p[c + 128], x2 = p[c + 256];
    float s = blk_sum<4>(x0 + x1 + x2);
    float mu = s * (1.f / Cc);
    float d0 = x0 - mu, d1 = x1 - mu, d2 = x2 - mu;
    float s2 = blk_sum<4>(d0 * d0 + d1 * d1 + d2 * d2);
    float w = rsqrtf(s2 * (1.f / Cc) + LN_EPS);
    size_t ro = (size_t)row * Cc;
    oh[ro + c]       = __float2half_rn(d0 * w * g[c]       + b[c]);
    oh[ro + c + 128] = __float2half_rn(d1 * w * g[c + 128] + b[c + 128]);
    oh[ro + c + 256] = __float2half_rn(d2 * w * g[c + 256] + b[c + 256]);
}

// ============================================================================
// fp16 single-pass GEMM, 2-stage cp.async pipeline, BK=64
// C[M,N] = A[M,K] @ B^T   A plain fp16 [M][K], B^T = Bh [N][K]
// Block 128x128, 256 threads, warp tile 64x32
// ============================================================================
#define GBM 128
#define GBN 128
#define GBK 64
#define LDS_K 72
#define MAT_H (GBM * LDS_K)             // halves per matrix tile (9216)
#define STAGE_H (2 * MAT_H)             // halves per stage (A + B)
#define STAGE_B (STAGE_H * 2)           // bytes per stage (36864)
#define GEMM_SMEM (2 * STAGE_B)         // 73728

__device__ __forceinline__ void mma16816(float* c, const unsigned* a, const unsigned* b) {
    asm volatile(
        "mma.sync.aligned.m16n8k16.row.col.f32.f16.f16.f32 "
        "{%0,%1,%2,%3}, {%4,%5,%6,%7}, {%8,%9}, {%0,%1,%2,%3};"
        : "+f"(c[0]), "+f"(c[1]), "+f"(c[2]), "+f"(c[3])
        : "r"(a[0]), "r"(a[1]), "r"(a[2]), "r"(a[3]), "r"(b[0]), "r"(b[1]));
}

__device__ __forceinline__ void cpa16(unsigned dst, const void* src, int szn) {
    asm volatile("cp.async.cg.shared.global [%0], [%1], 16, %2;"
                 :: "r"(dst), "l"(src), "r"(szn));
}

template <bool BIAS, bool RELU, bool RES, bool CVT, bool LSE>
__device__ __forceinline__ void bgemm_body(
    const fh* __restrict__ A_g, const fh* __restrict__ Bh_g,
    const float* __restrict__ bias, const float* __restrict__ res,
    float* __restrict__ Cf, fh* __restrict__ Oh,
    int M, int N, int K) {
    extern __shared__ fh sm[];
    unsigned sbase = (unsigned)__cvta_generic_to_shared(sm);

    int tid = threadIdx.x;
    int lane = tid & 31, warp = tid >> 5;
    int wm = warp & 1, wn = warp >> 1;
    int m0 = blockIdx.y * GBM, n0 = blockIdx.x * GBN;
    int g = lane >> 2, tg = lane & 3;

    float acc[4][4][4];
#pragma unroll
    for (int i = 0; i < 4; i++)
#pragma unroll
        for (int j = 0; j < 4; j++)
#pragma unroll
            for (int r = 0; r < 4; r++) acc[i][j][r] = 0.f;

    const int NT = K / GBK;

    auto load_tile = [&](int kt, int st) {
        int k0 = kt * GBK;
        unsigned sb = sbase + st * STAGE_B;
#pragma unroll
        for (int r = 0; r < 4; r++) {
            int cid = tid + r * 256;
            int row = cid >> 3, kch = (cid & 7) * 8;
            unsigned d = sb + (unsigned)(row * LDS_K + kch) * 2;
            size_t aoff = (size_t)(m0 + row) * K + k0 + kch;
            cpa16(d, A_g + aoff, 16);
            int bn = n0 + row;
            int ok = (bn < N) ? 16 : 0;
            size_t boff = (bn < N) ? ((size_t)bn * K + k0 + kch) : 0;
            cpa16(d + (unsigned)(MAT_H * 2), Bh_g + boff, ok);
        }
    };

    load_tile(0, 0);
    asm volatile("cp.async.commit_group;");

    for (int t = 0; t < NT; t++) {
        asm volatile("cp.async.wait_group 0;");
        __syncthreads();
        if (t + 1 < NT) {
            load_tile(t + 1, (t + 1) & 1);
            asm volatile("cp.async.commit_group;");
        }
        const fh* A_s  = sm + (t & 1) * STAGE_H;
        const fh* Bh_s = A_s + MAT_H;
#pragma unroll
        for (int kc = 0; kc < GBK; kc += 16) {
            unsigned ah[4][4], bh[4][2];
#pragma unroll
            for (int mt = 0; mt < 4; mt++) {
                int r = wm * 64 + mt * 16 + g;
                int base = r * LDS_K + kc + tg * 2;
                ah[mt][0] = *(const unsigned*)&A_s[base];
                ah[mt][1] = *(const unsigned*)&A_s[base + 8 * LDS_K];
                ah[mt][2] = *(const unsigned*)&A_s[base + 8];
                ah[mt][3] = *(const unsigned*)&A_s[base + 8 * LDS_K + 8];
            }
#pragma unroll
            for (int nt = 0; nt < 4; nt++) {
                int n = wn * 32 + nt * 8 + g;
                int base = n * LDS_K + kc + tg * 2;
                bh[nt][0] = *(const unsigned*)&Bh_s[base];
                bh[nt][1] = *(const unsigned*)&Bh_s[base + 8];
            }
#pragma unroll
            for (int mt = 0; mt < 4; mt++)
#pragma unroll
                for (int nt = 0; nt < 4; nt++) mma16816(acc[mt][nt], ah[mt], bh[nt]);
        }
        __syncthreads();
    }

    // epilogue (+ optional fused LSE partials for the LM head)
    float lsm[4][2], lss[4][2];
    if (LSE) {
#pragma unroll
        for (int mt = 0; mt < 4; mt++) {
            lsm[mt][0] = -1e30f; lsm[mt][1] = -1e30f;
            lss[mt][0] = 0.f;    lss[mt][1] = 0.f;
        }
    }
#pragma unroll
    for (int mt = 0; mt < 4; mt++) {
        int r = m0 + wm * 64 + mt * 16 + g;
#pragma unroll
        for (int nt = 0; nt < 4; nt++) {
            int c = n0 + wn * 32 + nt * 8 + tg * 2;
            if (c < N) {
                float v0 = acc[mt][nt][0], v1 = acc[mt][nt][1];
                float v2 = acc[mt][nt][2], v3 = acc[mt][nt][3];
                if (BIAS) { float b0 = bias[c], b1 = bias[c + 1]; v0 += b0; v1 += b1; v2 += b0; v3 += b1; }
                if (RELU) { v0 = fmaxf(v0, 0.f); v1 = fmaxf(v1, 0.f); v2 = fmaxf(v2, 0.f); v3 = fmaxf(v3, 0.f); }
                size_t o0 = (size_t)r * N + c, o1 = (size_t)(r + 8) * N + c;
                if (CVT) {
                    *(fh2*)(Oh + o0) = fh2(__float2half_rn(v0), __float2half_rn(v1));
                    *(fh2*)(Oh + o1) = fh2(__float2half_rn(v2), __float2half_rn(v3));
                } else {
                    if (RES) {
                        float2 r0 = *(const float2*)(res + o0), r1 = *(const float2*)(res + o1);
                        v0 += r0.x; v1 += r0.y; v2 += r1.x; v3 += r1.y;
                    }
                    *(float2*)(Cf + o0) = make_float2(v0, v1);
                    *(float2*)(Cf + o1) = make_float2(v2, v3);
                }
                if (LSE) {
                    lse_up(lsm[mt][0], lss[mt][0], v0);
                    lse_up(lsm[mt][0], lss[mt][0], v1);
                    lse_up(lsm[mt][1], lss[mt][1], v2);
                    lse_up(lsm[mt][1], lss[mt][1], v3);
                }
            }
        }
    }
    if (LSE) {
        __syncthreads();
        float2* part = (float2*)sm;   // [128][4]
#pragma unroll
        for (int mt = 0; mt < 4; mt++)
#pragma unroll
            for (int h2 = 0; h2 < 2; h2++) {
                float m = lsm[mt][h2], s = lss[mt][h2];
#pragma unroll
                for (int o = 1; o <= 2; o <<= 1) {
                    float m2 = __shfl_xor_sync(0xffffffffu, m, o);
                    float s2 = __shfl_xor_sync(0xffffffffu, s, o);
                    lse_merge(m, s, m2, s2);
                }
                if (tg == 0) {
                    int rl = wm * 64 + mt * 16 + g + h2 * 8;
                    part[rl * 4 + wn] = make_float2(m, s);
                }
            }
        __syncthreads();
        if (tid < 128) {
            float m = -1e30f, s = 0.f;
#pragma unroll
            for (int j = 0; j < 4; j++) {
                float2 p = part[tid * 4 + j];
                lse_merge(m, s, p.x, p.y);
            }
            g_lsep[(size_t)(m0 + tid) * NBLK_LM + blockIdx.x] = make_float2(m, s);
        }
    }
}

template <bool BIAS, bool RELU, bool RES, bool CVT, bool LSE>
__global__ void __launch_bounds__(256)
bgemm_kernel(const fh* A, const fh* Bh,
             const float* bias, const float* res, float* Cf, fh* Oh,
             int M, int N, int K) {
    bgemm_body<BIAS, RELU, RES, CVT, LSE>(A, Bh, bias, res, Cf, Oh, M, N, K);
}

// fused qkv via blockIdx.z: outputs fp16 q/k/v directly (CVT epilogue)
__global__ void __launch_bounds__(256)
qkv_kernel(const fh* A, const fh* qh, const fh* kh, const fh* vh,
           fh* oq, fh* ok, fh* ov, int M) {
    const fh* Bh = (blockIdx.z == 0) ? qh : (blockIdx.z == 1) ? kh : vh;
    fh* O = (blockIdx.z == 0) ? oq : (blockIdx.z == 1) ? ok : ov;
    bgemm_body<false, false, false, true, false>(A, Bh, nullptr, nullptr, nullptr, O,
                                                 M, Cc, Cc);
}

// ============================================================================
// Flash attention on HMMA fragments (R15 champion, unchanged).
// ============================================================================
#define AQK_LD 72
#define AVT_LD 136
#define ATT_SMEM ((2 * 128 * AQK_LD + 64 * AVT_LD) * 2)   // 54272 bytes

__global__ void __launch_bounds__(128)
attn_kernel(const fh* __restrict__ qg, const fh* __restrict__ kg,
            const fh* __restrict__ vg, fh* __restrict__ og) {
    extern __shared__ fh asm_[];
    fh* qs  = asm_;
    fh* ks  = asm_ + 128 * AQK_LD;
    fh* vts = asm_ + 2 * 128 * AQK_LD;
    int b = blockIdx.y, h = blockIdx.x;
    size_t base = (size_t)b * Tt * Cc + (size_t)h * DHh;
    int tid = threadIdx.x;

    for (int i = tid; i < 128 * 8; i += 128) {
        int row = i >> 3, c8 = (i & 7) * 8;
        *(uint4*)&qs[row * AQK_LD + c8] = *(const uint4*)(qg + base + (size_t)row * Cc + c8);
        *(uint4*)&ks[row * AQK_LD + c8] = *(const uint4*)(kg + base + (size_t)row * Cc + c8);
    }
    for (int i = tid; i < 128 * 32; i += 128) {
        int s = i >> 5, dp = (i & 31) * 2;
        fh2 vv = *(const fh2*)(vg + base + (size_t)s * Cc + dp);
        vts[dp * AVT_LD + s]       = vv.x;
        vts[(dp + 1) * AVT_LD + s] = vv.y;
    }
    __syncthreads();

    int lane = tid & 31, w = tid >> 5;
    int g = lane >> 2, tg = lane & 3;
    const float scale = 0.125f;

    unsigned qa[4][2][4];
#pragma unroll
    for (int kc4 = 0; kc4 < 4; kc4++)
#pragma unroll
        for (int mt = 0; mt < 2; mt++) {
            int r0 = w * 32 + mt * 16 + g;
            int cb = kc4 * 16 + tg * 2;
            qa[kc4][mt][0] = *(const unsigned*)&qs[r0 * AQK_LD + cb];
            qa[kc4][mt][1] = *(const unsigned*)&qs[(r0 + 8) * AQK_LD + cb];
            qa[kc4][mt][2] = *(const unsigned*)&qs[r0 * AQK_LD + cb + 8];
            qa[kc4][mt][3] = *(const unsigned*)&qs[(r0 + 8) * AQK_LD + cb + 8];
        }

    float oacc[2][8][4];
#pragma unroll
    for (int mt = 0; mt < 2; mt++)
#pragma unroll
        for (int dt = 0; dt < 8; dt++)
#pragma unroll
            for (int r = 0; r < 4; r++) oacc[mt][dt][r] = 0.f;
    float mrow[2][2] = {{-1e30f, -1e30f}, {-1e30f, -1e30f}};
    float lrow[2][2] = {{0.f, 0.f}, {0.f, 0.f}};

    int nit = 2 * w + 2;
    for (int it = 0; it < nit; it++) {
        float sfr[2][2][4];
#pragma unroll
        for (int mt = 0; mt < 2; mt++)
#pragma unroll
            for (int snt = 0; snt < 2; snt++) {
#pragma unroll
                for (int r = 0; r < 4; r++) sfr[mt][snt][r] = 0.f;
                int srow = it * 16 + snt * 8 + g;
#pragma unroll
                for (int kc4 = 0; kc4 < 4; kc4++) {
                    unsigned bb[2];
                    int cb = kc4 * 16 + tg * 2;
                    bb[0] = *(const unsigned*)&ks[srow * AQK_LD + cb];
                    bb[1] = *(const unsigned*)&ks[srow * AQK_LD + cb + 8];
                    mma16816(sfr[mt][snt], qa[kc4][mt], bb);
                }
            }
#pragma unroll
        for (int mt = 0; mt < 2; mt++) {
            float pp[2][4];
#pragma unroll
            for (int hf = 0; hf < 2; hf++) {
                int trow = w * 32 + mt * 16 + g + hf * 8;
                int c0 = it * 16 + tg * 2;
                int c2 = it * 16 + 8 + tg * 2;
                float v0 = sfr[mt][0][hf * 2] * scale;
                float v1 = sfr[mt][0][hf * 2 + 1] * scale;
                float v2 = sfr[mt][1][hf * 2] * scale;
                float v3 = sfr[mt][1][hf * 2 + 1] * scale;
                if (c0 > trow)     v0 = -1e30f;
                if (c0 + 1 > trow) v1 = -1e30f;
                if (c2 > trow)     v2 = -1e30f;
                if (c2 + 1 > trow) v3 = -1e30f;
                float cm = fmaxf(fmaxf(v0, v1), fmaxf(v2, v3));
                cm = fmaxf(cm, __shfl_xor_sync(0xffffffffu, cm, 1));
                cm = fmaxf(cm, __shfl_xor_sync(0xffffffffu, cm, 2));
                float mo = mrow[mt][hf];
                float mn = fmaxf(mo, cm);
                float f = __expf(mo - mn);
                float p0 = __expf(v0 - mn), p1 = __expf(v1 - mn);
                float p2 = __expf(v2 - mn), p3 = __expf(v3 - mn);
                float ps = p0 + p1 + p2 + p3;
                ps += __shfl_xor_sync(0xffffffffu, ps, 1);
                ps += __shfl_xor_sync(0xffffffffu, ps, 2);
                lrow[mt][hf] = lrow[mt][hf] * f + ps;
                mrow[mt][hf] = mn;
#pragma unroll
                for (int dt = 0; dt < 8; dt++) {
                    oacc[mt][dt][hf * 2]     *= f;
                    oacc[mt][dt][hf * 2 + 1] *= f;
                }
                pp[hf][0] = p0; pp[hf][1] = p1; pp[hf][2] = p2; pp[hf][3] = p3;
            }
            unsigned pa[4];
            {
                fh2 t0 = fh2(__float2half_rn(pp[0][0]), __float2half_rn(pp[0][1]));
                fh2 t1 = fh2(__float2half_rn(pp[1][0]), __float2half_rn(pp[1][1]));
                fh2 t2 = fh2(__float2half_rn(pp[0][2]), __float2half_rn(pp[0][3]));
                fh2 t3 = fh2(__float2half_rn(pp[1][2]), __float2half_rn(pp[1][3]));
                pa[0] = *(unsigned*)&t0; pa[1] = *(unsigned*)&t1;
                pa[2] = *(unsigned*)&t2; pa[3] = *(unsigned*)&t3;
            }
#pragma unroll
            for (int dt = 0; dt < 8; dt++) {
                unsigned bb[2];
                int vrow = dt * 8 + g;
                int sb = it * 16 + tg * 2;
                bb[0] = *(const unsigned*)&vts[vrow * AVT_LD + sb];
                bb[1] = *(const unsigned*)&vts[vrow * AVT_LD + sb + 8];
                mma16816(oacc[mt][dt], pa, bb);
            }
        }
    }

#pragma unroll
    for (int mt = 0; mt < 2; mt++)
#pragma unroll
        for (int hf = 0; hf < 2; hf++) {
            float inv = 1.f / lrow[mt][hf];
            int row = w * 32 + mt * 16 + g + hf * 8;
#pragma unroll
            for (int dt = 0; dt < 8; dt++) {
                fh2 o = fh2(__float2half_rn(oacc[mt][dt][hf * 2] * inv),
                            __float2half_rn(oacc[mt][dt][hf * 2 + 1] * inv));
                *(fh2*)(og + base + (size_t)row * Cc + dt * 8 + tg * 2) = o;
            }
        }
}

// ---------------- NLL finish from fused LSE partials ----------------
__global__ void nll_finish(const float* __restrict__ logits, const int* __restrict__ tgt) {
    int row = blockIdx.x;
    int lane = threadIdx.x;
    float m = -1e30f, s = 0.f;
    for (int j = lane; j < NBLK_LM; j += 32) {
        float2 p = g_lsep[(size_t)row * NBLK_LM + j];
        lse_merge(m, s, p.x, p.y);
    }
#pragma unroll
    for (int o = 16; o > 0; o >>= 1) {
        float m2 = __shfl_xor_sync(0xffffffffu, m, o);
        float s2 = __shfl_xor_sync(0xffffffffu, s, o);
        lse_merge(m, s, m2, s2);
    }
    if (lane == 0)
        g_nll[row] = -(logits[(size_t)row * Vv + tgt[row]] - m - logf(s));
}

__global__ void loss_kernel(float* __restrict__ out, int M, int write_loss) {
    float s = 0.f;
    for (int i = threadIdx.x; i < M; i += 256) s += g_nll[i];
    int lane = threadIdx.x & 31, w = threadIdx.x >> 5;
#pragma unroll
    for (int o = 16; o > 0; o >>= 1) s += __shfl_down_sync(0xffffffffu, s, o);
    __shared__ float sh[8];
    if (lane == 0) sh[w] = s;
    __syncthreads();
    if (threadIdx.x == 0 && write_loss) {
        float t = 0.f;
#pragma unroll
        for (int i = 0; i < 8; i++) t += sh[i];
        out[(size_t)M * Vv] = t / (float)M;
    }
}

// ---------------- launch ----------------
extern "C" void kernel_launch(void* const* d_in, const int* in_sizes, int n_in,
                              void* d_out, int out_size) {
    const int*   idx  = (const int*)d_in[0];
    const int*   tgt  = (const int*)d_in[1];
    const float* tok  = (const float*)d_in[2];
    const float* pos  = (const float*)d_in[3];
    const float* wq   = (const float*)d_in[4];
    const float* wk   = (const float*)d_in[5];
    const float* wv   = (const float*)d_in[6];
    const float* wo   = (const float*)d_in[7];
    const float* bo   = (const float*)d_in[8];
    const float* ln1g = (const float*)d_in[9];
    const float* ln1b = (const float*)d_in[10];
    const float* ln2g = (const float*)d_in[11];
    const float* ln2b = (const float*)d_in[12];
    const float* w1   = (const float*)d_in[13];
    const float* b1   = (const float*)d_in[14];
    const float* w2   = (const float*)d_in[15];
    const float* b2   = (const float*)d_in[16];
    const float* lnfg = (const float*)d_in[17];
    const float* lnfb = (const float*)d_in[18];
    const float* lmw  = (const float*)d_in[19];
    const float* lmb  = (const float*)d_in[20];
    float* out = (float*)d_out;

    int M  = in_sizes[0];
    int Bb = M / Tt;

    float* x;
    fh *q, *k, *v;
    fh *ha, *at, *ff;
    fh *wqh, *wkh, *wvh, *woh, *w1h, *w2h, *lmh;
    cudaGetSymbolAddress((void**)&x, g_x);
    cudaGetSymbolAddress((void**)&q, g_q);
    cudaGetSymbolAddress((void**)&k, g_k);
    cudaGetSymbolAddress((void**)&v, g_v);
    cudaGetSymbolAddress((void**)&ha, g_ha);
    cudaGetSymbolAddress((void**)&at, g_at);
    cudaGetSymbolAddress((void**)&ff, g_ff);
    cudaGetSymbolAddress((void**)&wqh, g_wqh);
    cudaGetSymbolAddress((void**)&wkh, g_wkh);
    cudaGetSymbolAddress((void**)&wvh, g_wvh);
    cudaGetSymbolAddress((void**)&woh, g_woh);
    cudaGetSymbolAddress((void**)&w1h, g_w1h);
    cudaGetSymbolAddress((void**)&w2h, g_w2h);
    cudaGetSymbolAddress((void**)&lmh, g_lmh);

    cudaFuncSetAttribute(attn_kernel, cudaFuncAttributeMaxDynamicSharedMemorySize, ATT_SMEM);
    cudaFuncSetAttribute(qkv_kernel, cudaFuncAttributeMaxDynamicSharedMemorySize, GEMM_SMEM);
    cudaFuncSetAttribute(bgemm_kernel<true, false, true, false, false>,
                         cudaFuncAttributeMaxDynamicSharedMemorySize, GEMM_SMEM);
    cudaFuncSetAttribute(bgemm_kernel<true, true, false, true, false>,
                         cudaFuncAttributeMaxDynamicSharedMemorySize, GEMM_SMEM);
    cudaFuncSetAttribute(bgemm_kernel<true, false, false, false, true>,
                         cudaFuncAttributeMaxDynamicSharedMemorySize, GEMM_SMEM);

    dim3 tb(32, 8);
    dim3 blk(256);

    // ---- launch order: 6th launch (ncu -s 5 -c 1) is the layer-0 qkv GEMM ----
    embed_kernel<<<M, Cc>>>(idx, tok, pos);                               // 1
    wsplit_t<<<dim3(Cc / 32, Cc / 32, Ll), tb>>>(wq, wqh, Cc, Cc);        // 2
    wsplit_t<<<dim3(Cc / 32, Cc / 32, Ll), tb>>>(wk, wkh, Cc, Cc);        // 3
    wsplit_t<<<dim3(Cc / 32, Cc / 32, Ll), tb>>>(wv, wvh, Cc, Cc);        // 4
    ln_h_kernel<<<M, 128>>>(x, ln1g, ln1b, ha);                           // 5
    qkv_kernel<<<dim3(Cc / GBN, M / GBM, 3), blk, GEMM_SMEM>>>(           // 6 <- profiled
        ha, wqh, wkh, wvh, q, k, v, M);
    wsplit_t<<<dim3(Cc / 32, Cc / 32, Ll), tb>>>(wo, woh, Cc, Cc);
    wsplit_t<<<dim3(FFf / 32, Cc / 32, Ll), tb>>>(w1, w1h, Cc, FFf);
    wsplit_t<<<dim3(Cc / 32, FFf / 32, Ll), tb>>>(w2, w2h, FFf, Cc);
    wsplit_t<<<dim3((Vv + 31) / 32, Cc / 32, 1), tb>>>(lmw, lmh, Cc, Vv);

    for (int l = 0; l < Ll; l++) {
        size_t wofs = (size_t)l * Cc * Cc;
        size_t f1 = (size_t)l * Cc * FFf;
        if (l > 0) {
            ln_h_kernel<<<M, 128>>>(x, ln1g + l * Cc, ln1b + l * Cc, ha);
            qkv_kernel<<<dim3(Cc / GBN, M / GBM, 3), blk, GEMM_SMEM>>>(
                ha, wqh + wofs, wkh + wofs, wvh + wofs, q, k, v, M);
        }
        attn_kernel<<<dim3(Hh, Bb), 128, ATT_SMEM>>>(q, k, v, at);
        bgemm_kernel<true, false, true, false, false><<<dim3(Cc / GBN, M / GBM), blk, GEMM_SMEM>>>(
            at, woh + wofs, bo + l * Cc, x, x, nullptr, M, Cc, Cc);
        ln_h_kernel<<<M, 128>>>(x, ln2g + l * Cc, ln2b + l * Cc, ha);
        bgemm_kernel<true, true, false, true, false><<<dim3(FFf / GBN, M / GBM), blk, GEMM_SMEM>>>(
            ha, w1h + f1, b1 + l * FFf, nullptr, nullptr, ff, M, FFf, Cc);
        bgemm_kernel<true, false, true, false, false><<<dim3(Cc / GBN, M / GBM), blk, GEMM_SMEM>>>(
            ff, w2h + f1, b2 + l * Cc, x, x, nullptr, M, Cc, FFf);
    }

    ln_h_kernel<<<M, 128>>>(x, lnfg, lnfb, ha);
    bgemm_kernel<true, false, false, false, true><<<dim3((Vv + GBN - 1) / GBN, M / GBM), blk, GEMM_SMEM>>>(
        ha, lmh, lmb, nullptr, out, nullptr, M, Vv, Cc);

    nll_finish<<<M, 32>>>(out, tgt);
    int wr = ((long long)out_size > (long long)M * (long long)Vv) ? 1 : 0;
    loss_kernel<<<1, 256>>>(out, M, wr);
}

// round 17
// speedup vs baseline: 1.6359x; 1.0823x over previous
#include <cuda_runtime.h>
#include <cuda_fp16.h>

#define Bsz  64
#define Tt   128
#define Cc   384
#define Hh   6
#define DHh  64
#define Ll   6
#define FFf  1536
#define Vv   25000
#define NTOK (Bsz * Tt)
#define LN_EPS 1e-5f
#define NBLK_LM 196              // ceil(25000/128)

typedef __half fh;
typedef __half2 fh2;

// ---------------- scratch (device globals: allocation-free) ----------------
__device__ float g_x[NTOK * Cc];
__device__ fh    g_q[NTOK * Cc];
__device__ fh    g_k[NTOK * Cc];
__device__ fh    g_v[NTOK * Cc];
__device__ float g_nll[NTOK];
__device__ float2 g_lsep[(size_t)NTOK * NBLK_LM];

// fp16 activations
__device__ fh g_ha[NTOK * Cc];       // LN outputs
__device__ fh g_at[NTOK * Cc];       // attention outputs
__device__ fh g_ff[NTOK * FFf];      // FFN1 outputs

// transposed fp16 weights [N][K]
__device__ fh g_wqh[Ll * Cc * Cc];
__device__ fh g_wkh[Ll * Cc * Cc];
__device__ fh g_wvh[Ll * Cc * Cc];
__device__ fh g_woh[Ll * Cc * Cc];
__device__ fh g_w1h[Ll * Cc * FFf];
__device__ fh g_w2h[Ll * FFf * Cc];
__device__ fh g_lmh[(size_t)Vv * Cc];

__device__ __forceinline__ void lse_up(float& m, float& s, float v) {
    if (v > m) { s = s * __expf(m - v) + 1.f; m = v; }
    else       { s += __expf(v - m); }
}
__device__ __forceinline__ void lse_merge(float& m, float& s, float m2, float s2) {
    float nm = fmaxf(m, m2);
    s = s * __expf(m - nm) + s2 * __expf(m2 - nm);
    m = nm;
}

// ---------------- weight transpose: w[K][N] -> th[N][K] fp16 ----------------
__global__ void wsplit_t(const float* __restrict__ w, fh* __restrict__ th,
                         int K, int N) {
    __shared__ float tile[32][33];
    int l = blockIdx.z;
    const float* wp = w + (size_t)l * K * N;
    fh* thp = th + (size_t)l * K * N;
    int n0 = blockIdx.x * 32, k0 = blockIdx.y * 32;
    int tx = threadIdx.x, ty = threadIdx.y;  // 32 x 8
#pragma unroll
    for (int i = 0; i < 4; i++) {
        int k = k0 + ty + 8 * i, n = n0 + tx;
        tile[ty + 8 * i][tx] = (k < K && n < N) ? wp[(size_t)k * N + n] : 0.f;
    }
    __syncthreads();
#pragma unroll
    for (int i = 0; i < 4; i++) {
        int n = n0 + ty + 8 * i, k = k0 + tx;
        if (n < N && k < K)
            thp[(size_t)n * K + k] = __float2half_rn(tile[tx][ty + 8 * i]);
    }
}

// ---------------- embedding ----------------
__global__ void embed_kernel(const int* __restrict__ idx,
                             const float* __restrict__ tok,
                             const float* __restrict__ pos) {
    int i = blockIdx.x, c = threadIdx.x;
    int t = i % Tt;
    g_x[(size_t)i * Cc + c] = tok[(size_t)idx[i] * Cc + c] + pos[(size_t)t * Cc + c];
}

// ---------------- layernorm -> fp16 ----------------
template <int NW>
__device__ __forceinline__ float blk_sum(float v) {
    __shared__ float sh[NW];
    int lane = threadIdx.x & 31, w = threadIdx.x >> 5;
#pragma unroll
    for (int o = 16; o > 0; o >>= 1) v += __shfl_down_sync(0xffffffffu, v, o);
    if (lane == 0) sh[w] = v;
    __syncthreads();
    if (threadIdx.x == 0) {
        float t = 0.f;
#pragma unroll
        for (int i = 0; i < NW; i++) t += sh[i];
        sh[0] = t;
    }
    __syncthreads();
    float r = sh[0];
    __syncthreads();
    return r;
}

__global__ void ln_h_kernel(const float* __restrict__ in, const float* __restrict__ g,
                            const float* __restrict__ b, fh* __restrict__ oh) {
    int row = blockIdx.x;
    const float* p = in + (size_t)row * Cc;
    int c = threadIdx.x;
    float x0 = p[c], x1 = p[c + 128], x2 = p[c + 256];
    float s = blk_sum<4>(x0 + x1 + x2);
    float mu = s * (1.f / Cc);
    float d0 = x0 - mu, d1 = x1 - mu, d2 = x2 - mu;
    float s2 = blk_sum<4>(d0 * d0 + d1 * d1 + d2 * d2);
    float w = rsqrtf(s2 * (1.f / Cc) + LN_EPS);
    size_t ro = (size_t)row * Cc;
    oh[ro + c]       = __float2half_rn(d0 * w * g[c]       + b[c]);
    oh[ro + c + 128] = __float2half_rn(d1 * w * g[c + 128] + b[c + 128]);
    oh[ro + c + 256] = __float2half_rn(d2 * w * g[c + 256] + b[c + 256]);
}

// ============================================================================
// fp16 single-pass GEMM, 2-stage cp.async pipeline, BK=64
// C[M,N] = A[M,K] @ B^T   A plain fp16 [M][K], B^T = Bh [N][K]
// Block 128x128, 256 threads, warp tile 64x32, forced 2 CTAs/SM
// ============================================================================
#define GBM 128
#define GBN 128
#define GBK 64
#define LDS_K 72
#define MAT_H (GBM * LDS_K)             // halves per matrix tile (9216)
#define STAGE_H (2 * MAT_H)             // halves per stage (A + B)
#define STAGE_B (STAGE_H * 2)           // bytes per stage (36864)
#define GEMM_SMEM (2 * STAGE_B)         // 73728

__device__ __forceinline__ void mma16816(float* c, const unsigned* a, const unsigned* b) {
    asm volatile(
        "mma.sync.aligned.m16n8k16.row.col.f32.f16.f16.f32 "
        "{%0,%1,%2,%3}, {%4,%5,%6,%7}, {%8,%9}, {%0,%1,%2,%3};"
        : "+f"(c[0]), "+f"(c[1]), "+f"(c[2]), "+f"(c[3])
        : "r"(a[0]), "r"(a[1]), "r"(a[2]), "r"(a[3]), "r"(b[0]), "r"(b[1]));
}

__device__ __forceinline__ void cpa16(unsigned dst, const void* src, int szn) {
    asm volatile("cp.async.cg.shared.global [%0], [%1], 16, %2;"
                 :: "r"(dst), "l"(src), "r"(szn));
}

template <bool BIAS, bool RELU, bool RES, bool CVT, bool LSE>
__device__ __forceinline__ void bgemm_body(
    const fh* __restrict__ A_g, const fh* __restrict__ Bh_g,
    const float* __restrict__ bias, const float* __restrict__ res,
    float* __restrict__ Cf, fh* __restrict__ Oh,
    int M, int N, int K) {
    extern __shared__ fh sm[];
    unsigned sbase = (unsigned)__cvta_generic_to_shared(sm);

    int tid = threadIdx.x;
    int lane = tid & 31, warp = tid >> 5;
    int wm = warp & 1, wn = warp >> 1;
    int m0 = blockIdx.y * GBM, n0 = blockIdx.x * GBN;
    int g = lane >> 2, tg = lane & 3;

    float acc[4][4][4];
#pragma unroll
    for (int i = 0; i < 4; i++)
#pragma unroll
        for (int j = 0; j < 4; j++)
#pragma unroll
            for (int r = 0; r < 4; r++) acc[i][j][r] = 0.f;

    const int NT = K / GBK;

    auto load_tile = [&](int kt, int st) {
        int k0 = kt * GBK;
        unsigned sb = sbase + st * STAGE_B;
#pragma unroll
        for (int r = 0; r < 4; r++) {
            int cid = tid + r * 256;
            int row = cid >> 3, kch = (cid & 7) * 8;
            unsigned d = sb + (unsigned)(row * LDS_K + kch) * 2;
            size_t aoff = (size_t)(m0 + row) * K + k0 + kch;
            cpa16(d, A_g + aoff, 16);
            int bn = n0 + row;
            int ok = (bn < N) ? 16 : 0;
            size_t boff = (bn < N) ? ((size_t)bn * K + k0 + kch) : 0;
            cpa16(d + (unsigned)(MAT_H * 2), Bh_g + boff, ok);
        }
    };

    load_tile(0, 0);
    asm volatile("cp.async.commit_group;");

    for (int t = 0; t < NT; t++) {
        asm volatile("cp.async.wait_group 0;");
        __syncthreads();
        if (t + 1 < NT) {
            load_tile(t + 1, (t + 1) & 1);
            asm volatile("cp.async.commit_group;");
        }
        const fh* A_s  = sm + (t & 1) * STAGE_H;
        const fh* Bh_s = A_s + MAT_H;
#pragma unroll
        for (int kc = 0; kc < GBK; kc += 16) {
            unsigned ah[4][4], bh[4][2];
#pragma unroll
            for (int mt = 0; mt < 4; mt++) {
                int r = wm * 64 + mt * 16 + g;
                int base = r * LDS_K + kc + tg * 2;
                ah[mt][0] = *(const unsigned*)&A_s[base];
                ah[mt][1] = *(const unsigned*)&A_s[base + 8 * LDS_K];
                ah[mt][2] = *(const unsigned*)&A_s[base + 8];
                ah[mt][3] = *(const unsigned*)&A_s[base + 8 * LDS_K + 8];
            }
#pragma unroll
            for (int nt = 0; nt < 4; nt++) {
                int n = wn * 32 + nt * 8 + g;
                int base = n * LDS_K + kc + tg * 2;
                bh[nt][0] = *(const unsigned*)&Bh_s[base];
                bh[nt][1] = *(const unsigned*)&Bh_s[base + 8];
            }
#pragma unroll
            for (int mt = 0; mt < 4; mt++)
#pragma unroll
                for (int nt = 0; nt < 4; nt++) mma16816(acc[mt][nt], ah[mt], bh[nt]);
        }
        __syncthreads();
    }

    // epilogue (+ optional fused LSE partials for the LM head)
    float lsm[4][2], lss[4][2];
    if (LSE) {
#pragma unroll
        for (int mt = 0; mt < 4; mt++) {
            lsm[mt][0] = -1e30f; lsm[mt][1] = -1e30f;
            lss[mt][0] = 0.f;    lss[mt][1] = 0.f;
        }
    }
#pragma unroll
    for (int mt = 0; mt < 4; mt++) {
        int r = m0 + wm * 64 + mt * 16 + g;
#pragma unroll
        for (int nt = 0; nt < 4; nt++) {
            int c = n0 + wn * 32 + nt * 8 + tg * 2;
            if (c < N) {
                float v0 = acc[mt][nt][0], v1 = acc[mt][nt][1];
                float v2 = acc[mt][nt][2], v3 = acc[mt][nt][3];
                if (BIAS) { float b0 = bias[c], b1 = bias[c + 1]; v0 += b0; v1 += b1; v2 += b0; v3 += b1; }
                if (RELU) { v0 = fmaxf(v0, 0.f); v1 = fmaxf(v1, 0.f); v2 = fmaxf(v2, 0.f); v3 = fmaxf(v3, 0.f); }
                size_t o0 = (size_t)r * N + c, o1 = (size_t)(r + 8) * N + c;
                if (CVT) {
                    *(fh2*)(Oh + o0) = fh2(__float2half_rn(v0), __float2half_rn(v1));
                    *(fh2*)(Oh + o1) = fh2(__float2half_rn(v2), __float2half_rn(v3));
                } else {
                    if (RES) {
                        float2 r0 = *(const float2*)(res + o0), r1 = *(const float2*)(res + o1);
                        v0 += r0.x; v1 += r0.y; v2 += r1.x; v3 += r1.y;
                    }
                    *(float2*)(Cf + o0) = make_float2(v0, v1);
                    *(float2*)(Cf + o1) = make_float2(v2, v3);
                }
                if (LSE) {
                    lse_up(lsm[mt][0], lss[mt][0], v0);
                    lse_up(lsm[mt][0], lss[mt][0], v1);
                    lse_up(lsm[mt][1], lss[mt][1], v2);
                    lse_up(lsm[mt][1], lss[mt][1], v3);
                }
            }
        }
    }
    if (LSE) {
        __syncthreads();
        float2* part = (float2*)sm;   // [128][4]
#pragma unroll
        for (int mt = 0; mt < 4; mt++)
#pragma unroll
            for (int h2 = 0; h2 < 2; h2++) {
                float m = lsm[mt][h2], s = lss[mt][h2];
#pragma unroll
                for (int o = 1; o <= 2; o <<= 1) {
                    float m2 = __shfl_xor_sync(0xffffffffu, m, o);
                    float s2 = __shfl_xor_sync(0xffffffffu, s, o);
                    lse_merge(m, s, m2, s2);
                }
                if (tg == 0) {
                    int rl = wm * 64 + mt * 16 + g + h2 * 8;
                    part[rl * 4 + wn] = make_float2(m, s);
                }
            }
        __syncthreads();
        if (tid < 128) {
            float m = -1e30f, s = 0.f;
#pragma unroll
            for (int j = 0; j < 4; j++) {
                float2 p = part[tid * 4 + j];
                lse_merge(m, s, p.x, p.y);
            }
            g_lsep[(size_t)(m0 + tid) * NBLK_LM + blockIdx.x] = make_float2(m, s);
        }
    }
}

template <bool BIAS, bool RELU, bool RES, bool CVT, bool LSE>
__global__ void __launch_bounds__(256, 2)
bgemm_kernel(const fh* A, const fh* Bh,
             const float* bias, const float* res, float* Cf, fh* Oh,
             int M, int N, int K) {
    bgemm_body<BIAS, RELU, RES, CVT, LSE>(A, Bh, bias, res, Cf, Oh, M, N, K);
}

// fused qkv via blockIdx.z: outputs fp16 q/k/v directly (CVT epilogue)
__global__ void __launch_bounds__(256, 2)
qkv_kernel(const fh* A, const fh* qh, const fh* kh, const fh* vh,
           fh* oq, fh* ok, fh* ov, int M) {
    const fh* Bh = (blockIdx.z == 0) ? qh : (blockIdx.z == 1) ? kh : vh;
    fh* O = (blockIdx.z == 0) ? oq : (blockIdx.z == 1) ? ok : ov;
    bgemm_body<false, false, false, true, false>(A, Bh, nullptr, nullptr, nullptr, O,
                                                 M, Cc, Cc);
}

// ============================================================================
// Flash attention on HMMA fragments (champion, unchanged).
// ============================================================================
#define AQK_LD 72
#define AVT_LD 136
#define ATT_SMEM ((2 * 128 * AQK_LD + 64 * AVT_LD) * 2)   // 54272 bytes

__global__ void __launch_bounds__(128)
attn_kernel(const fh* __restrict__ qg, const fh* __restrict__ kg,
            const fh* __restrict__ vg, fh* __restrict__ og) {
    extern __shared__ fh asm_[];
    fh* qs  = asm_;
    fh* ks  = asm_ + 128 * AQK_LD;
    fh* vts = asm_ + 2 * 128 * AQK_LD;
    int b = blockIdx.y, h = blockIdx.x;
    size_t base = (size_t)b * Tt * Cc + (size_t)h * DHh;
    int tid = threadIdx.x;

    for (int i = tid; i < 128 * 8; i += 128) {
        int row = i >> 3, c8 = (i & 7) * 8;
        *(uint4*)&qs[row * AQK_LD + c8] = *(const uint4*)(qg + base + (size_t)row * Cc + c8);
        *(uint4*)&ks[row * AQK_LD + c8] = *(const uint4*)(kg + base + (size_t)row * Cc + c8);
    }
    for (int i = tid; i < 128 * 32; i += 128) {
        int s = i >> 5, dp = (i & 31) * 2;
        fh2 vv = *(const fh2*)(vg + base + (size_t)s * Cc + dp);
        vts[dp * AVT_LD + s]       = vv.x;
        vts[(dp + 1) * AVT_LD + s] = vv.y;
    }
    __syncthreads();

    int lane = tid & 31, w = tid >> 5;
    int g = lane >> 2, tg = lane & 3;
    const float scale = 0.125f;

    unsigned qa[4][2][4];
#pragma unroll
    for (int kc4 = 0; kc4 < 4; kc4++)
#pragma unroll
        for (int mt = 0; mt < 2; mt++) {
            int r0 = w * 32 + mt * 16 + g;
            int cb = kc4 * 16 + tg * 2;
            qa[kc4][mt][0] = *(const unsigned*)&qs[r0 * AQK_LD + cb];
            qa[kc4][mt][1] = *(const unsigned*)&qs[(r0 + 8) * AQK_LD + cb];
            qa[kc4][mt][2] = *(const unsigned*)&qs[r0 * AQK_LD + cb + 8];
            qa[kc4][mt][3] = *(const unsigned*)&qs[(r0 + 8) * AQK_LD + cb + 8];
        }

    float oacc[2][8][4];
#pragma unroll
    for (int mt = 0; mt < 2; mt++)
#pragma unroll
        for (int dt = 0; dt < 8; dt++)
#pragma unroll
            for (int r = 0; r < 4; r++) oacc[mt][dt][r] = 0.f;
    float mrow[2][2] = {{-1e30f, -1e30f}, {-1e30f, -1e30f}};
    float lrow[2][2] = {{0.f, 0.f}, {0.f, 0.f}};

    int nit = 2 * w + 2;
    for (int it = 0; it < nit; it++) {
        float sfr[2][2][4];
#pragma unroll
        for (int mt = 0; mt < 2; mt++)
#pragma unroll
            for (int snt = 0; snt < 2; snt++) {
#pragma unroll
                for (int r = 0; r < 4; r++) sfr[mt][snt][r] = 0.f;
                int srow = it * 16 + snt * 8 + g;
#pragma unroll
                for (int kc4 = 0; kc4 < 4; kc4++) {
                    unsigned bb[2];
                    int cb = kc4 * 16 + tg * 2;
                    bb[0] = *(const unsigned*)&ks[srow * AQK_LD + cb];
                    bb[1] = *(const unsigned*)&ks[srow * AQK_LD + cb + 8];
                    mma16816(sfr[mt][snt], qa[kc4][mt], bb);
                }
            }
#pragma unroll
        for (int mt = 0; mt < 2; mt++) {
            float pp[2][4];
#pragma unroll
            for (int hf = 0; hf < 2; hf++) {
                int trow = w * 32 + mt * 16 + g + hf * 8;
                int c0 = it * 16 + tg * 2;
                int c2 = it * 16 + 8 + tg * 2;
                float v0 = sfr[mt][0][hf * 2] * scale;
                float v1 = sfr[mt][0][hf * 2 + 1] * scale;
                float v2 = sfr[mt][1][hf * 2] * scale;
                float v3 = sfr[mt][1][hf * 2 + 1] * scale;
                if (c0 > trow)     v0 = -1e30f;
                if (c0 + 1 > trow) v1 = -1e30f;
                if (c2 > trow)     v2 = -1e30f;
                if (c2 + 1 > trow) v3 = -1e30f;
                float cm = fmaxf(fmaxf(v0, v1), fmaxf(v2, v3));
                cm = fmaxf(cm, __shfl_xor_sync(0xffffffffu, cm, 1));
                cm = fmaxf(cm, __shfl_xor_sync(0xffffffffu, cm, 2));
                float mo = mrow[mt][hf];
                float mn = fmaxf(mo, cm);
                float f = __expf(mo - mn);
                float p0 = __expf(v0 - mn), p1 = __expf(v1 - mn);
                float p2 = __expf(v2 - mn), p3 = __expf(v3 - mn);
                float ps = p0 + p1 + p2 + p3;
                ps += __shfl_xor_sync(0xffffffffu, ps, 1);
                ps += __shfl_xor_sync(0xffffffffu, ps, 2);
                lrow[mt][hf] = lrow[mt][hf] * f + ps;
                mrow[mt][hf] = mn;
#pragma unroll
                for (int dt = 0; dt < 8; dt++) {
                    oacc[mt][dt][hf * 2]     *= f;
                    oacc[mt][dt][hf * 2 + 1] *= f;
                }
                pp[hf][0] = p0; pp[hf][1] = p1; pp[hf][2] = p2; pp[hf][3] = p3;
            }
            unsigned pa[4];
            {
                fh2 t0 = fh2(__float2half_rn(pp[0][0]), __float2half_rn(pp[0][1]));
                fh2 t1 = fh2(__float2half_rn(pp[1][0]), __float2half_rn(pp[1][1]));
                fh2 t2 = fh2(__float2half_rn(pp[0][2]), __float2half_rn(pp[0][3]));
                fh2 t3 = fh2(__float2half_rn(pp[1][2]), __float2half_rn(pp[1][3]));
                pa[0] = *(unsigned*)&t0; pa[1] = *(unsigned*)&t1;
                pa[2] = *(unsigned*)&t2; pa[3] = *(unsigned*)&t3;
            }
#pragma unroll
            for (int dt = 0; dt < 8; dt++) {
                unsigned bb[2];
                int vrow = dt * 8 + g;
                int sb = it * 16 + tg * 2;
                bb[0] = *(const unsigned*)&vts[vrow * AVT_LD + sb];
                bb[1] = *(const unsigned*)&vts[vrow * AVT_LD + sb + 8];
                mma16816(oacc[mt][dt], pa, bb);
            }
        }
    }

#pragma unroll
    for (int mt = 0; mt < 2; mt++)
#pragma unroll
        for (int hf = 0; hf < 2; hf++) {
            float inv = 1.f / lrow[mt][hf];
            int row = w * 32 + mt * 16 + g + hf * 8;
#pragma unroll
            for (int dt = 0; dt < 8; dt++) {
                fh2 o = fh2(__float2half_rn(oacc[mt][dt][hf * 2] * inv),
                            __float2half_rn(oacc[mt][dt][hf * 2 + 1] * inv));
                *(fh2*)(og + base + (size_t)row * Cc + dt * 8 + tg * 2) = o;
            }
        }
}

// ---------------- NLL finish from fused LSE partials ----------------
__global__ void nll_finish(const float* __restrict__ logits, const int* __restrict__ tgt) {
    int row = blockIdx.x;
    int lane = threadIdx.x;
    float m = -1e30f, s = 0.f;
    for (int j = lane; j < NBLK_LM; j += 32) {
        float2 p = g_lsep[(size_t)row * NBLK_LM + j];
        lse_merge(m, s, p.x, p.y);
    }
#pragma unroll
    for (int o = 16; o > 0; o >>= 1) {
        float m2 = __shfl_xor_sync(0xffffffffu, m, o);
        float s2 = __shfl_xor_sync(0xffffffffu, s, o);
        lse_merge(m, s, m2, s2);
    }
    if (lane == 0)
        g_nll[row] = -(logits[(size_t)row * Vv + tgt[row]] - m - logf(s));
}

__global__ void loss_kernel(float* __restrict__ out, int M, int write_loss) {
    float s = 0.f;
    for (int i = threadIdx.x; i < M; i += 256) s += g_nll[i];
    int lane = threadIdx.x & 31, w = threadIdx.x >> 5;
#pragma unroll
    for (int o = 16; o > 0; o >>= 1) s += __shfl_down_sync(0xffffffffu, s, o);
    __shared__ float sh[8];
    if (lane == 0) sh[w] = s;
    __syncthreads();
    if (threadIdx.x == 0 && write_loss) {
        float t = 0.f;
#pragma unroll
        for (int i = 0; i < 8; i++) t += sh[i];
        out[(size_t)M * Vv] = t / (float)M;
    }
}

// ---------------- launch ----------------
extern "C" void kernel_launch(void* const* d_in, const int* in_sizes, int n_in,
                              void* d_out, int out_size) {
    const int*   idx  = (const int*)d_in[0];
    const int*   tgt  = (const int*)d_in[1];
    const float* tok  = (const float*)d_in[2];
    const float* pos  = (const float*)d_in[3];
    const float* wq   = (const float*)d_in[4];
    const float* wk   = (const float*)d_in[5];
    const float* wv   = (const float*)d_in[6];
    const float* wo   = (const float*)d_in[7];
    const float* bo   = (const float*)d_in[8];
    const float* ln1g = (const float*)d_in[9];
    const float* ln1b = (const float*)d_in[10];
    const float* ln2g = (const float*)d_in[11];
    const float* ln2b = (const float*)d_in[12];
    const float* w1   = (const float*)d_in[13];
    const float* b1   = (const float*)d_in[14];
    const float* w2   = (const float*)d_in[15];
    const float* b2   = (const float*)d_in[16];
    const float* lnfg = (const float*)d_in[17];
    const float* lnfb = (const float*)d_in[18];
    const float* lmw  = (const float*)d_in[19];
    const float* lmb  = (const float*)d_in[20];
    float* out = (float*)d_out;

    int M  = in_sizes[0];
    int Bb = M / Tt;

    float* x;
    fh *q, *k, *v;
    fh *ha, *at, *ff;
    fh *wqh, *wkh, *wvh, *woh, *w1h, *w2h, *lmh;
    cudaGetSymbolAddress((void**)&x, g_x);
    cudaGetSymbolAddress((void**)&q, g_q);
    cudaGetSymbolAddress((void**)&k, g_k);
    cudaGetSymbolAddress((void**)&v, g_v);
    cudaGetSymbolAddress((void**)&ha, g_ha);
    cudaGetSymbolAddress((void**)&at, g_at);
    cudaGetSymbolAddress((void**)&ff, g_ff);
    cudaGetSymbolAddress((void**)&wqh, g_wqh);
    cudaGetSymbolAddress((void**)&wkh, g_wkh);
    cudaGetSymbolAddress((void**)&wvh, g_wvh);
    cudaGetSymbolAddress((void**)&woh, g_woh);
    cudaGetSymbolAddress((void**)&w1h, g_w1h);
    cudaGetSymbolAddress((void**)&w2h, g_w2h);
    cudaGetSymbolAddress((void**)&lmh, g_lmh);

    cudaFuncSetAttribute(attn_kernel, cudaFuncAttributeMaxDynamicSharedMemorySize, ATT_SMEM);
    cudaFuncSetAttribute(qkv_kernel, cudaFuncAttributeMaxDynamicSharedMemorySize, GEMM_SMEM);
    cudaFuncSetAttribute(bgemm_kernel<true, false, true, false, false>,
                         cudaFuncAttributeMaxDynamicSharedMemorySize, GEMM_SMEM);
    cudaFuncSetAttribute(bgemm_kernel<true, true, false, true, false>,
                         cudaFuncAttributeMaxDynamicSharedMemorySize, GEMM_SMEM);
    cudaFuncSetAttribute(bgemm_kernel<true, false, false, false, true>,
                         cudaFuncAttributeMaxDynamicSharedMemorySize, GEMM_SMEM);

    dim3 tb(32, 8);
    dim3 blk(256);

    // ---- launch order: 6th launch (ncu -s 5 -c 1) is the layer-0 qkv GEMM ----
    embed_kernel<<<M, Cc>>>(idx, tok, pos);                               // 1
    wsplit_t<<<dim3(Cc / 32, Cc / 32, Ll), tb>>>(wq, wqh, Cc, Cc);        // 2
    wsplit_t<<<dim3(Cc / 32, Cc / 32, Ll), tb>>>(wk, wkh, Cc, Cc);        // 3
    wsplit_t<<<dim3(Cc / 32, Cc / 32, Ll), tb>>>(wv, wvh, Cc, Cc);        // 4
    ln_h_kernel<<<M, 128>>>(x, ln1g, ln1b, ha);                           // 5
    qkv_kernel<<<dim3(Cc / GBN, M / GBM, 3), blk, GEMM_SMEM>>>(           // 6 <- profiled
        ha, wqh, wkh, wvh, q, k, v, M);
    wsplit_t<<<dim3(Cc / 32, Cc / 32, Ll), tb>>>(wo, woh, Cc, Cc);
    wsplit_t<<<dim3(FFf / 32, Cc / 32, Ll), tb>>>(w1, w1h, Cc, FFf);
    wsplit_t<<<dim3(Cc / 32, FFf / 32, Ll), tb>>>(w2, w2h, FFf, Cc);
    wsplit_t<<<dim3((Vv + 31) / 32, Cc / 32, 1), tb>>>(lmw, lmh, Cc, Vv);

    for (int l = 0; l < Ll; l++) {
        size_t wofs = (size_t)l * Cc * Cc;
        size_t f1 = (size_t)l * Cc * FFf;
        if (l > 0) {
            ln_h_kernel<<<M, 128>>>(x, ln1g + l * Cc, ln1b + l * Cc, ha);
            qkv_kernel<<<dim3(Cc / GBN, M / GBM, 3), blk, GEMM_SMEM>>>(
                ha, wqh + wofs, wkh + wofs, wvh + wofs, q, k, v, M);
        }
        attn_kernel<<<dim3(Hh, Bb), 128, ATT_SMEM>>>(q, k, v, at);
        bgemm_kernel<true, false, true, false, false><<<dim3(Cc / GBN, M / GBM), blk, GEMM_SMEM>>>(
            at, woh + wofs, bo + l * Cc, x, x, nullptr, M, Cc, Cc);
        ln_h_kernel<<<M, 128>>>(x, ln2g + l * Cc, ln2b + l * Cc, ha);
        bgemm_kernel<true, true, false, true, false><<<dim3(FFf / GBN, M / GBM), blk, GEMM_SMEM>>>(
            ha, w1h + f1, b1 + l * FFf, nullptr, nullptr, ff, M, FFf, Cc);
        bgemm_kernel<true, false, true, false, false><<<dim3(Cc / GBN, M / GBM), blk, GEMM_SMEM>>>(
            ff, w2h + f1, b2 + l * Cc, x, x, nullptr, M, Cc, FFf);
    }

    ln_h_kernel<<<M, 128>>>(x, lnfg, lnfb, ha);
    bgemm_kernel<true, false, false, false, true><<<dim3((Vv + GBN - 1) / GBN, M / GBM), blk, GEMM_SMEM>>>(
        ha, lmh, lmb, nullptr, out, nullptr, M, Vv, Cc);

    nll_finish<<<M, 32>>>(out, tgt);
    int wr = ((long long)out_size > (long long)M * (long long)Vv) ? 1 : 0;
    loss_kernel<<<1, 256>>>(out, M, wr);
}